// round 7
// baseline (speedup 1.0000x reference)
#include <cuda_runtime.h>
#include <math.h>

#define NN 512
#define DD 128
#define NROWS (NN*NN)
typedef unsigned long long ull;

__device__ float g_x[NROWS*DD];     // normed x; later reused for tri
__device__ float g_to[NROWS*DD];
__device__ float g_from[NROWS*DD];
__device__ float g_og[NROWS*DD];
__device__ int   g_mode;

static __device__ __forceinline__ ull ffma2(ull a, ull b, ull c) {
    ull d; asm("fma.rn.f32x2 %0, %1, %2, %3;" : "=l"(d) : "l"(a), "l"(b), "l"(c)); return d;
}
static __device__ __forceinline__ void unpk(ull v, float& a, float& b) {
    asm("mov.b64 {%0, %1}, %2;" : "=f"(a), "=f"(b) : "l"(v));
}
static __device__ __forceinline__ float sigm(float x) { return 1.0f / (1.0f + __expf(-x)); }

// ---- mask dtype detection: 0=u8, 1=i32, 2=f32, 3=bf16 ----
__global__ void k_detect(const unsigned int* __restrict__ m) {
    __shared__ int c[4];
    int t = threadIdx.x;
    if (t < 4) c[t] = 0;
    __syncthreads();
    int cb = 0, cf = 0, ci = 0, co = 0;
    for (int i = t; i < 65536; i += 256) {
        unsigned v = m[i];
        if (!v) continue;
        if (v == 0x3F803F80u || v == 0x00003F80u) cb++;
        else if (v == 0x3F800000u) cf++;
        else if (v == 1u) ci++;
        else co++;
    }
    atomicAdd(&c[0], cb); atomicAdd(&c[1], cf); atomicAdd(&c[2], ci); atomicAdd(&c[3], co);
    __syncthreads();
    if (t == 0) {
        int mode;
        if      (c[0] > 64) mode = 3;
        else if (c[3] > 64) mode = 0;
        else if (c[1] > 64) mode = 2;
        else                mode = 1;
        g_mode = mode;
    }
}
static __device__ __forceinline__ float mask_at(const void* m, int mode, int idx) {
    if (mode == 2) return ((const float*)m)[idx] != 0.0f ? 1.0f : 0.0f;
    if (mode == 0) return ((const unsigned char*)m)[idx] ? 1.0f : 0.0f;
    if (mode == 1) return ((const int*)m)[idx] ? 1.0f : 0.0f;
    return ((const unsigned short*)m)[idx] ? 1.0f : 0.0f;
}

// ---- Stage 1: LN1 over d ----
__global__ __launch_bounds__(128) void k_ln(const float* __restrict__ edges,
                                            const float* __restrict__ w,
                                            const float* __restrict__ b) {
    __shared__ float sA[4], sB[4];
    int t = threadIdx.x;
    int r = blockIdx.x;
    float e = edges[(size_t)r * DD + t];
    float s = e, q = e * e;
    #pragma unroll
    for (int o = 16; o; o >>= 1) {
        s += __shfl_xor_sync(0xffffffffu, s, o);
        q += __shfl_xor_sync(0xffffffffu, q, o);
    }
    if ((t & 31) == 0) { sA[t >> 5] = s; sB[t >> 5] = q; }
    __syncthreads();
    s = sA[0] + sA[1] + sA[2] + sA[3];
    q = sB[0] + sB[1] + sB[2] + sB[3];
    float mu = s * (1.0f / DD);
    float var = q * (1.0f / DD) - mu * mu;
    float rs = rsqrtf(var + 1e-5f);
    g_x[(size_t)r * DD + t] = (e - mu) * rs * w[t] + b[t];
}

// ---- Stage 2: fused projection (fg + out_gate), gating + mask epilogue ----
// grid.x: 0..7 -> fg feat/gate pairs (32 feat cols + their 32 gates); 8..9 -> go.
// BM=128 rows, BN=64 cols, K=128 single pass. dyn smem: xs[128][128]+ws[64][130].
__global__ __launch_bounds__(256) void k_fg(const void*  __restrict__ mask,
                                            const float* __restrict__ Wfg,
                                            const float* __restrict__ bfg,
                                            const float* __restrict__ Wgo,
                                            const float* __restrict__ bgo) {
    extern __shared__ float dsm[];
    float* xs = dsm;               // [128][128]
    float* ws = dsm + 128 * 128;   // [64][130]
    const int tid = threadIdx.x;
    const int nt = blockIdx.x;
    const int row0 = blockIdx.y * 128;
    const int mode = g_mode;

    #pragma unroll
    for (int p = 0; p < 16; p++) {
        int idx = tid + 256 * p;            // 4096 float4
        int rr = idx >> 5, k4 = idx & 31;
        float4 v = *(const float4*)&g_x[(size_t)(row0 + rr) * DD + k4 * 4];
        *(float4*)&xs[rr * 128 + k4 * 4] = v;
    }
    #pragma unroll
    for (int p = 0; p < 8; p++) {
        int idx = tid + 256 * p;            // 2048 float4
        int rowj = idx >> 5, k4 = idx & 31;
        const float* src;
        if (nt < 8) {
            int e = (rowj < 32) ? (nt * 32 + rowj) : (256 + nt * 32 + (rowj - 32));
            src = Wfg + (size_t)e * DD;
        } else {
            src = Wgo + (size_t)((nt - 8) * 64 + rowj) * DD;
        }
        float4 v = *(const float4*)(src + k4 * 4);
        float* d = &ws[rowj * 130 + k4 * 4];
        d[0] = v.x; d[1] = v.y; d[2] = v.z; d[3] = v.w;
    }
    __syncthreads();

    const int tm = tid >> 4, tx = tid & 15;
    ull acc[8][4];
    #pragma unroll
    for (int a = 0; a < 8; a++)
        #pragma unroll
        for (int c = 0; c < 4; c++) acc[a][c] = 0ull;

    #pragma unroll 4
    for (int k2 = 0; k2 < 64; k2++) {
        ull xp[8], wp[4];
        #pragma unroll
        for (int a = 0; a < 8; a++) xp[a] = *(const ull*)&xs[(tm + 16 * a) * 128 + 2 * k2];
        #pragma unroll
        for (int c = 0; c < 4; c++) wp[c] = *(const ull*)&ws[(tx + 16 * c) * 130 + 2 * k2];
        #pragma unroll
        for (int a = 0; a < 8; a++)
            #pragma unroll
            for (int c = 0; c < 4; c++) acc[a][c] = ffma2(xp[a], wp[c], acc[a][c]);
    }

    if (nt < 8) {
        float bf0 = bfg[nt * 32 + tx],        bf1 = bfg[nt * 32 + tx + 16];
        float bg0 = bfg[256 + nt * 32 + tx],  bg1 = bfg[256 + nt * 32 + tx + 16];
        int f0 = nt * 32 + tx, f1 = f0 + 16;
        #pragma unroll
        for (int a = 0; a < 8; a++) {
            int r = row0 + tm + 16 * a;
            float mv = mask_at(mask, mode, r);
            float lo, hi, d0, d1, d2, d3;
            unpk(acc[a][0], lo, hi); d0 = lo + hi;
            unpk(acc[a][1], lo, hi); d1 = lo + hi;
            unpk(acc[a][2], lo, hi); d2 = lo + hi;
            unpk(acc[a][3], lo, hi); d3 = lo + hi;
            float v0 = (d0 + bf0) * sigm(d2 + bg0) * mv;
            float v1 = (d1 + bf1) * sigm(d3 + bg1) * mv;
            size_t base = (size_t)r * DD;
            if (f0 < 128) { g_to[base + f0] = v0; g_to[base + f1] = v1; }
            else          { g_from[base + f0 - 128] = v0; g_from[base + f1 - 128] = v1; }
        }
    } else {
        int e0 = (nt - 8) * 64 + tx;
        float bv[4] = { bgo[e0], bgo[e0 + 16], bgo[e0 + 32], bgo[e0 + 48] };
        #pragma unroll
        for (int a = 0; a < 8; a++) {
            int r = row0 + tm + 16 * a;
            float mv = mask_at(mask, mode, r);
            size_t base = (size_t)r * DD;
            #pragma unroll
            for (int c = 0; c < 4; c++) {
                float lo, hi; unpk(acc[a][c], lo, hi);
                g_og[base + e0 + 16 * c] = sigm(lo + hi + bv[c]) * mv;
            }
        }
    }
}

// ---- Stage 3: tri[i,j,d] = sum_k to[i,k,d]*from[j,k,d]; tile 64x64x4d, K-slab 8 ----
__global__ __launch_bounds__(256) void k_tri() {
    __shared__ __align__(16) float to_s[8 * 64 * 6];
    __shared__ __align__(16) float fr_s[8 * 64 * 6];
    const int tid = threadIdx.x;
    const int tx = tid & 15, ty = tid >> 4;
    const int j0 = blockIdx.x * 64, i0 = blockIdx.y * 64, d0 = blockIdx.z * 4;

    ull acc[4][4][2];
    #pragma unroll
    for (int a = 0; a < 4; a++)
        #pragma unroll
        for (int b = 0; b < 4; b++) { acc[a][b][0] = 0ull; acc[a][b][1] = 0ull; }

    for (int kp = 0; kp < NN / 8; kp++) {
        __syncthreads();
        #pragma unroll
        for (int p = 0; p < 2; p++) {
            int idx = tid + 256 * p;        // 512
            int ii = idx & 63, kk = idx >> 6;
            int kg = kp * 8 + kk;
            float4 tv = *(const float4*)&g_to[(size_t)((i0 + ii) * NN + kg) * DD + d0];
            float* d = &to_s[(kk * 64 + ii) * 6];
            d[0] = tv.x; d[1] = tv.y; d[2] = tv.z; d[3] = tv.w;
            float4 fv = *(const float4*)&g_from[(size_t)((j0 + ii) * NN + kg) * DD + d0];
            float* e = &fr_s[(kk * 64 + ii) * 6];
            e[0] = fv.x; e[1] = fv.y; e[2] = fv.z; e[3] = fv.w;
        }
        __syncthreads();
        #pragma unroll
        for (int kk = 0; kk < 8; kk++) {
            ull ta[4][2], fb[4][2];
            #pragma unroll
            for (int a = 0; a < 4; a++) {
                const float* p = &to_s[(kk * 64 + ty + 16 * a) * 6];
                ta[a][0] = *(const ull*)p; ta[a][1] = *(const ull*)(p + 2);
                const float* q = &fr_s[(kk * 64 + tx + 16 * a) * 6];
                fb[a][0] = *(const ull*)q; fb[a][1] = *(const ull*)(q + 2);
            }
            #pragma unroll
            for (int a = 0; a < 4; a++)
                #pragma unroll
                for (int b = 0; b < 4; b++) {
                    acc[a][b][0] = ffma2(ta[a][0], fb[b][0], acc[a][b][0]);
                    acc[a][b][1] = ffma2(ta[a][1], fb[b][1], acc[a][b][1]);
                }
        }
    }
    #pragma unroll
    for (int a = 0; a < 4; a++)
        #pragma unroll
        for (int b = 0; b < 4; b++) {
            float4 o;
            unpk(acc[a][b][0], o.x, o.y);
            unpk(acc[a][b][1], o.z, o.w);
            int ii = i0 + ty + 16 * a, jj = j0 + tx + 16 * b;
            *(float4*)&g_x[(size_t)(ii * NN + jj) * DD + d0] = o;
        }
}

// ---- Stage 4: LN2(tri) @ W_out^T + b_out, times out_gate ----
// BM=64 rows, BN=64 cols (grid.x=2 halves), dyn smem ys[64][130]+ws[64][130].
__global__ __launch_bounds__(256) void k_out(const float* __restrict__ ln2w,
                                             const float* __restrict__ ln2b,
                                             const float* __restrict__ Wout,
                                             const float* __restrict__ bout,
                                             float* __restrict__ out) {
    extern __shared__ float dsm[];
    float* ys = dsm;              // [64][130] normed tri
    float* ws = dsm + 64 * 130;   // [64][130] Wout rows (output d cols)
    const int tid = threadIdx.x;
    const int col0 = blockIdx.x * 64;
    const int row0 = blockIdx.y * 64;

    #pragma unroll
    for (int p = 0; p < 8; p++) {
        int idx = tid + 256 * p;            // 2048 float4
        int rowj = idx >> 5, k4 = idx & 31;
        float4 v = *(const float4*)&Wout[(size_t)(col0 + rowj) * DD + k4 * 4];
        float* d = &ws[rowj * 130 + k4 * 4];
        d[0] = v.x; d[1] = v.y; d[2] = v.z; d[3] = v.w;
    }

    {   // LN2: warp w handles rows w*8..w*8+7; lane covers h = lane*4..+3
        int warp = tid >> 5, lane = tid & 31;
        float w4[4], b4[4];
        #pragma unroll
        for (int q = 0; q < 4; q++) { w4[q] = ln2w[lane * 4 + q]; b4[q] = ln2b[lane * 4 + q]; }
        #pragma unroll
        for (int rr = 0; rr < 8; rr++) {
            int lrow = warp * 8 + rr;
            float4 v = *(const float4*)&g_x[(size_t)(row0 + lrow) * DD + lane * 4];
            float s = v.x + v.y + v.z + v.w;
            float q2 = v.x * v.x + v.y * v.y + v.z * v.z + v.w * v.w;
            #pragma unroll
            for (int o = 16; o; o >>= 1) {
                s  += __shfl_xor_sync(0xffffffffu, s, o);
                q2 += __shfl_xor_sync(0xffffffffu, q2, o);
            }
            float mu = s * (1.0f / DD);
            float var = q2 * (1.0f / DD) - mu * mu;
            float rs = rsqrtf(var + 1e-5f);
            float* d = &ys[lrow * 130 + lane * 4];
            d[0] = (v.x - mu) * rs * w4[0] + b4[0];
            d[1] = (v.y - mu) * rs * w4[1] + b4[1];
            d[2] = (v.z - mu) * rs * w4[2] + b4[2];
            d[3] = (v.w - mu) * rs * w4[3] + b4[3];
        }
    }
    __syncthreads();

    const int tm = tid >> 4, tx = tid & 15;
    ull acc[4][4];
    #pragma unroll
    for (int a = 0; a < 4; a++)
        #pragma unroll
        for (int c = 0; c < 4; c++) acc[a][c] = 0ull;

    #pragma unroll 4
    for (int k2 = 0; k2 < 64; k2++) {
        ull yp[4], wp[4];
        #pragma unroll
        for (int a = 0; a < 4; a++) yp[a] = *(const ull*)&ys[(tm + 16 * a) * 130 + 2 * k2];
        #pragma unroll
        for (int c = 0; c < 4; c++) wp[c] = *(const ull*)&ws[(tx + 16 * c) * 130 + 2 * k2];
        #pragma unroll
        for (int a = 0; a < 4; a++)
            #pragma unroll
            for (int c = 0; c < 4; c++) acc[a][c] = ffma2(yp[a], wp[c], acc[a][c]);
    }

    #pragma unroll
    for (int a = 0; a < 4; a++) {
        int r = row0 + tm + 16 * a;
        size_t base = (size_t)r * DD;
        #pragma unroll
        for (int c = 0; c < 4; c++) {
            int col = col0 + tx + 16 * c;
            float lo, hi; unpk(acc[a][c], lo, hi);
            out[base + col] = g_og[base + col] * (lo + hi + bout[col]);
        }
    }
}

extern "C" void kernel_launch(void* const* d_in, const int* in_sizes, int n_in,
                              void* d_out, int out_size) {
    const float* edges = (const float*)d_in[0];
    const void*  mask  = d_in[1];
    const float* ln1w  = (const float*)d_in[2];
    const float* ln1b  = (const float*)d_in[3];
    const float* Wfg   = (const float*)d_in[4];
    const float* bfg   = (const float*)d_in[5];
    const float* Wgo   = (const float*)d_in[6];
    const float* bgo   = (const float*)d_in[7];
    const float* ln2w  = (const float*)d_in[8];
    const float* ln2b  = (const float*)d_in[9];
    const float* Wout  = (const float*)d_in[10];
    const float* bout  = (const float*)d_in[11];
    float* out = (float*)d_out;

    cudaFuncSetAttribute(k_fg,  cudaFuncAttributeMaxDynamicSharedMemorySize, 98816);
    cudaFuncSetAttribute(k_out, cudaFuncAttributeMaxDynamicSharedMemorySize, 66560);

    k_detect<<<1, 256>>>((const unsigned int*)mask);
    k_ln<<<NROWS, 128>>>(edges, ln1w, ln1b);
    k_fg<<<dim3(10, NROWS / 128), 256, 98816>>>(mask, Wfg, bfg, Wgo, bgo);
    k_tri<<<dim3(NN / 64, NN / 64, DD / 4), 256>>>();
    k_out<<<dim3(2, NROWS / 64), 256, 66560>>>(ln2w, ln2b, Wout, bout, out);
}

// round 11
// speedup vs baseline: 1.4770x; 1.4770x over previous
#include <cuda_runtime.h>
#include <cuda_bf16.h>
#include <math.h>
#include <stdint.h>

#define NN 512
#define DD 128
#define NROWS (NN*NN)
typedef unsigned long long ull;

// ---- scratch (device globals; allocation is forbidden) ----
__device__ float g_x[NROWS*DD];                 // normed x [row][d]; later reused as tri planar [d][i*NN+j]
__device__ float g_og[NROWS*DD];                // out_gate [row][d]
__device__ __nv_bfloat16 g_to_hi[(size_t)DD*NROWS];
__device__ __nv_bfloat16 g_to_lo[(size_t)DD*NROWS];
__device__ __nv_bfloat16 g_fr_hi[(size_t)DD*NROWS];
__device__ __nv_bfloat16 g_fr_lo[(size_t)DD*NROWS];
__device__ int g_mode;

static __device__ __forceinline__ ull ffma2(ull a, ull b, ull c) {
    ull d; asm("fma.rn.f32x2 %0, %1, %2, %3;" : "=l"(d) : "l"(a), "l"(b), "l"(c)); return d;
}
static __device__ __forceinline__ void unpk(ull v, float& a, float& b) {
    asm("mov.b64 {%0, %1}, %2;" : "=f"(a), "=f"(b) : "l"(v));
}
static __device__ __forceinline__ float sigm(float x) { return 1.0f / (1.0f + __expf(-x)); }

static __device__ __forceinline__ uint32_t smem_u32(const void* p) {
    uint32_t a;
    asm("{ .reg .u64 t; cvta.to.shared.u64 t, %1; cvt.u32.u64 %0, t; }" : "=r"(a) : "l"(p));
    return a;
}

// ---- baseline-PTX tensor ops (no sm_103a-gated instructions) ----
static __device__ __forceinline__ void ldsm_x4(uint32_t* r, uint32_t addr) {
    asm volatile("ldmatrix.sync.aligned.m8n8.x4.shared.b16 {%0,%1,%2,%3}, [%4];"
                 : "=r"(r[0]), "=r"(r[1]), "=r"(r[2]), "=r"(r[3]) : "r"(addr));
}
static __device__ __forceinline__ void ldsm_x2(uint32_t* r, uint32_t addr) {
    asm volatile("ldmatrix.sync.aligned.m8n8.x2.shared.b16 {%0,%1}, [%2];"
                 : "=r"(r[0]), "=r"(r[1]) : "r"(addr));
}
static __device__ __forceinline__ void mma_bf16(float* c, const uint32_t* a, const uint32_t* b) {
    asm volatile("mma.sync.aligned.m16n8k16.row.col.f32.bf16.bf16.f32 "
                 "{%0,%1,%2,%3}, {%4,%5,%6,%7}, {%8,%9}, {%0,%1,%2,%3};"
                 : "+f"(c[0]), "+f"(c[1]), "+f"(c[2]), "+f"(c[3])
                 : "r"(a[0]), "r"(a[1]), "r"(a[2]), "r"(a[3]), "r"(b[0]), "r"(b[1]));
}

// ---- mask dtype detection: 0=u8, 1=i32, 2=f32, 3=bf16 ----
__global__ void k_detect(const unsigned int* __restrict__ m) {
    __shared__ int c[4];
    int t = threadIdx.x;
    if (t < 4) c[t] = 0;
    __syncthreads();
    int cb = 0, cf = 0, ci = 0, co = 0;
    for (int i = t; i < 65536; i += 256) {
        unsigned v = m[i];
        if (!v) continue;
        if (v == 0x3F803F80u || v == 0x00003F80u) cb++;
        else if (v == 0x3F800000u) cf++;
        else if (v == 1u) ci++;
        else co++;
    }
    atomicAdd(&c[0], cb); atomicAdd(&c[1], cf); atomicAdd(&c[2], ci); atomicAdd(&c[3], co);
    __syncthreads();
    if (t == 0) {
        int mode;
        if      (c[0] > 64) mode = 3;
        else if (c[3] > 64) mode = 0;
        else if (c[1] > 64) mode = 2;
        else                mode = 1;
        g_mode = mode;
    }
}
static __device__ __forceinline__ float mask_at(const void* m, int mode, int idx) {
    if (mode == 2) return ((const float*)m)[idx] != 0.0f ? 1.0f : 0.0f;
    if (mode == 0) return ((const unsigned char*)m)[idx] ? 1.0f : 0.0f;
    if (mode == 1) return ((const int*)m)[idx] ? 1.0f : 0.0f;
    return ((const unsigned short*)m)[idx] ? 1.0f : 0.0f;
}

// ---- Stage 1: LN1 over d ----
__global__ __launch_bounds__(128) void k_ln(const float* __restrict__ edges,
                                            const float* __restrict__ w,
                                            const float* __restrict__ b) {
    __shared__ float sA[4], sB[4];
    int t = threadIdx.x;
    int r = blockIdx.x;
    float e = edges[(size_t)r * DD + t];
    float s = e, q = e * e;
    #pragma unroll
    for (int o = 16; o; o >>= 1) {
        s += __shfl_xor_sync(0xffffffffu, s, o);
        q += __shfl_xor_sync(0xffffffffu, q, o);
    }
    if ((t & 31) == 0) { sA[t >> 5] = s; sB[t >> 5] = q; }
    __syncthreads();
    s = sA[0] + sA[1] + sA[2] + sA[3];
    q = sB[0] + sB[1] + sB[2] + sB[3];
    float mu = s * (1.0f / DD);
    float var = q * (1.0f / DD) - mu * mu;
    float rs = rsqrtf(var + 1e-5f);
    g_x[(size_t)r * DD + t] = (e - mu) * rs * w[t] + b[t];
}

// ---- Stage 2: fused projection (fg + out_gate) ----
// grid.x 0..7: feat/gate pairs -> bf16-split planar to/from; 8..9: out_gate -> g_og row-major.
// BM=128 rows, BN=64 cols, K=128. dyn smem: xs[128][130] + ws[64][130] = 99840 B.
__global__ __launch_bounds__(256) void k_fg(const void*  __restrict__ mask,
                                            const float* __restrict__ Wfg,
                                            const float* __restrict__ bfg,
                                            const float* __restrict__ Wgo,
                                            const float* __restrict__ bgo) {
    extern __shared__ float dsm[];
    float* xs = dsm;               // [128][130]
    float* ws = dsm + 128 * 130;   // [64][130]
    const int tid = threadIdx.x;
    const int nt = blockIdx.x;
    const int row0 = blockIdx.y * 128;
    const int mode = g_mode;

    #pragma unroll
    for (int p = 0; p < 16; p++) {
        int idx = tid + 256 * p;            // 4096 float4 slots
        int rr = idx >> 5, k4 = idx & 31;
        float4 v = *(const float4*)&g_x[(size_t)(row0 + rr) * DD + k4 * 4];
        float* d = &xs[rr * 130 + k4 * 4];
        *(float2*)d       = make_float2(v.x, v.y);
        *(float2*)(d + 2) = make_float2(v.z, v.w);
    }
    #pragma unroll
    for (int p = 0; p < 8; p++) {
        int idx = tid + 256 * p;            // 2048 float4 slots
        int rowj = idx >> 5, k4 = idx & 31;
        const float* src;
        if (nt < 8) {
            int e = (rowj < 32) ? (nt * 32 + rowj) : (256 + nt * 32 + (rowj - 32));
            src = Wfg + (size_t)e * DD;
        } else {
            src = Wgo + (size_t)((nt - 8) * 64 + rowj) * DD;
        }
        float4 v = *(const float4*)(src + k4 * 4);
        float* d = &ws[rowj * 130 + k4 * 4];
        d[0] = v.x; d[1] = v.y; d[2] = v.z; d[3] = v.w;
    }
    __syncthreads();

    // fg blocks: consecutive threads on consecutive ROWS (planar stores coalesce);
    // go blocks: consecutive threads on cols (g_og row-major stores coalesce).
    int tm, tx;
    if (nt < 8) { tm = tid & 15;  tx = tid >> 4; }
    else        { tm = tid >> 4;  tx = tid & 15; }

    ull acc[8][4];
    #pragma unroll
    for (int a = 0; a < 8; a++)
        #pragma unroll
        for (int c = 0; c < 4; c++) acc[a][c] = 0ull;

    #pragma unroll 4
    for (int k2 = 0; k2 < 64; k2++) {
        ull xp[8], wp[4];
        #pragma unroll
        for (int a = 0; a < 8; a++) xp[a] = *(const ull*)&xs[(tm + 16 * a) * 130 + 2 * k2];
        #pragma unroll
        for (int c = 0; c < 4; c++) wp[c] = *(const ull*)&ws[(tx + 16 * c) * 130 + 2 * k2];
        #pragma unroll
        for (int a = 0; a < 8; a++)
            #pragma unroll
            for (int c = 0; c < 4; c++) acc[a][c] = ffma2(xp[a], wp[c], acc[a][c]);
    }

    if (nt < 8) {
        int f0 = nt * 32 + tx, f1 = f0 + 16;
        float bf0 = bfg[f0],       bf1 = bfg[f1];
        float bg0 = bfg[256 + f0], bg1 = bfg[256 + f1];
        __nv_bfloat16* hi0; __nv_bfloat16* lo0; __nv_bfloat16* hi1; __nv_bfloat16* lo1;
        if (nt < 4) {
            hi0 = g_to_hi + (size_t)f0 * NROWS;         lo0 = g_to_lo + (size_t)f0 * NROWS;
            hi1 = g_to_hi + (size_t)f1 * NROWS;         lo1 = g_to_lo + (size_t)f1 * NROWS;
        } else {
            hi0 = g_fr_hi + (size_t)(f0 - 128) * NROWS; lo0 = g_fr_lo + (size_t)(f0 - 128) * NROWS;
            hi1 = g_fr_hi + (size_t)(f1 - 128) * NROWS; lo1 = g_fr_lo + (size_t)(f1 - 128) * NROWS;
        }
        #pragma unroll
        for (int a = 0; a < 8; a++) {
            int r = row0 + tm + 16 * a;
            float mv = mask_at(mask, mode, r);
            float lo, hi, d0, d1, d2, d3;
            unpk(acc[a][0], lo, hi); d0 = lo + hi;
            unpk(acc[a][1], lo, hi); d1 = lo + hi;
            unpk(acc[a][2], lo, hi); d2 = lo + hi;
            unpk(acc[a][3], lo, hi); d3 = lo + hi;
            float v0 = (d0 + bf0) * sigm(d2 + bg0) * mv;
            float v1 = (d1 + bf1) * sigm(d3 + bg1) * mv;
            __nv_bfloat16 h0 = __float2bfloat16(v0);
            __nv_bfloat16 l0 = __float2bfloat16(v0 - __bfloat162float(h0));
            __nv_bfloat16 h1 = __float2bfloat16(v1);
            __nv_bfloat16 l1 = __float2bfloat16(v1 - __bfloat162float(h1));
            hi0[r] = h0; lo0[r] = l0; hi1[r] = h1; lo1[r] = l1;
        }
    } else {
        int e0 = (nt - 8) * 64 + tx;
        float bv[4] = { bgo[e0], bgo[e0 + 16], bgo[e0 + 32], bgo[e0 + 48] };
        #pragma unroll
        for (int a = 0; a < 8; a++) {
            int r = row0 + tm + 16 * a;
            float mv = mask_at(mask, mode, r);
            size_t base = (size_t)r * DD;
            #pragma unroll
            for (int c = 0; c < 4; c++) {
                float lo, hi; unpk(acc[a][c], lo, hi);
                g_og[base + e0 + 16 * c] = sigm(lo + hi + bv[c]) * mv;
            }
        }
    }
}

// ---- Stage 3: tri via mma.sync (HMMA, baseline PTX) ----
// Per CTA: 128x128 output tile of one d-plane. D = A@B^T, A=to_d [128x512] K-major,
// B=from_d [128x512] K-major -> mma row.col directly. 8 K-slabs of 64.
// 3 bf16-split passes (AhBh + AhBl + AlBh) share fp32 register accumulators.
// Warp grid 2(m) x 4(n); warp tile 64x32 = 4x4 m16n8 tiles.
#define TRI_SMEM 65536
__global__ __launch_bounds__(256) void k_tri() {
    extern __shared__ char smc[];
    const uint32_t sb = smem_u32(smc);
    const int tid = threadIdx.x;
    const int wid = tid >> 5, lane = tid & 31;
    const int j0 = blockIdx.x * 128, i0 = blockIdx.y * 128, d = blockIdx.z;
    const int wm = wid >> 2, wn = wid & 3;

    float acc[4][4][4];
    #pragma unroll
    for (int mt = 0; mt < 4; mt++)
        #pragma unroll
        for (int nt = 0; nt < 4; nt++)
            #pragma unroll
            for (int q = 0; q < 4; q++) acc[mt][nt][q] = 0.0f;

    const __nv_bfloat16* srcs[4] = {
        g_to_hi + (size_t)d * NROWS + (size_t)i0 * NN,
        g_to_lo + (size_t)d * NROWS + (size_t)i0 * NN,
        g_fr_hi + (size_t)d * NROWS + (size_t)j0 * NN,
        g_fr_lo + (size_t)d * NROWS + (size_t)j0 * NN
    };

    for (int kp = 0; kp < 8; kp++) {
        int k0 = kp * 64;
        #pragma unroll
        for (int t = 0; t < 4; t++) {
            const __nv_bfloat16* s = srcs[t] + k0;
            char* dst = smc + t * 16384;
            #pragma unroll
            for (int p = 0; p < 4; p++) {
                int idx = tid + 256 * p;          // 1024 uint4 per 128x64 bf16 tile
                int row = idx >> 3, c = idx & 7;
                uint4 v = *(const uint4*)(s + (size_t)row * NN + c * 8);
                uint32_t off = (row << 7) + (c << 4);
                off ^= (off >> 3) & 0x70;
                *(uint4*)(dst + off) = v;
            }
        }
        __syncthreads();

        #pragma unroll
        for (int ks = 0; ks < 4; ks++) {
            uint32_t a_hi[4][4], a_lo[4][4];
            #pragma unroll
            for (int mt = 0; mt < 4; mt++) {
                // x4: lanes map (lane&15)->row within 16, (lane>>4)->k halves (8 bf16 = 16B)
                uint32_t off = (uint32_t)((wm * 64 + mt * 16 + (lane & 15)) << 7)
                             + (uint32_t)(ks * 32) + ((uint32_t)(lane >> 4) << 4);
                off ^= (off >> 3) & 0x70;
                ldsm_x4(a_hi[mt], sb + off);
                ldsm_x4(a_lo[mt], sb + 16384 + off);
            }
            uint32_t b_hi[4][2], b_lo[4][2];
            #pragma unroll
            for (int nt = 0; nt < 4; nt++) {
                // x2: lanes 0-15 map (lane&7)->n row, ((lane>>3)&1)->k half
                uint32_t off = (uint32_t)((wn * 32 + nt * 8 + (lane & 7)) << 7)
                             + (uint32_t)(ks * 32) + ((uint32_t)((lane >> 3) & 1) << 4);
                off ^= (off >> 3) & 0x70;
                ldsm_x2(b_hi[nt], sb + 32768 + off);
                ldsm_x2(b_lo[nt], sb + 49152 + off);
            }
            #pragma unroll
            for (int mt = 0; mt < 4; mt++)
                #pragma unroll
                for (int nt = 0; nt < 4; nt++) {
                    mma_bf16(acc[mt][nt], a_hi[mt], b_hi[nt]);
                    mma_bf16(acc[mt][nt], a_hi[mt], b_lo[nt]);
                    mma_bf16(acc[mt][nt], a_lo[mt], b_hi[nt]);
                }
        }
        __syncthreads();
    }

    // epilogue: c0,c1 -> (row, col..col+1); c2,c3 -> (row+8, col..col+1)
    #pragma unroll
    for (int mt = 0; mt < 4; mt++) {
        int i = i0 + wm * 64 + mt * 16 + (lane >> 2);
        #pragma unroll
        for (int nt = 0; nt < 4; nt++) {
            int j = j0 + wn * 32 + nt * 8 + (lane & 3) * 2;
            size_t base = (size_t)d * NROWS + (size_t)i * NN + j;
            *(float2*)&g_x[base]          = make_float2(acc[mt][nt][0], acc[mt][nt][1]);
            *(float2*)&g_x[base + 8 * NN] = make_float2(acc[mt][nt][2], acc[mt][nt][3]);
        }
    }
}

// ---- Stage 4: LN2(tri planar) @ W_out^T + b_out, times out_gate ----
__global__ __launch_bounds__(256) void k_out(const float* __restrict__ ln2w,
                                             const float* __restrict__ ln2b,
                                             const float* __restrict__ Wout,
                                             const float* __restrict__ bout,
                                             float* __restrict__ out) {
    extern __shared__ float dsm[];
    float* ys = dsm;              // [64][130]
    float* ws = dsm + 64 * 130;   // [64][130]
    const int tid = threadIdx.x;
    const int col0 = blockIdx.x * 64;
    const int row0 = blockIdx.y * 64;

    #pragma unroll
    for (int p = 0; p < 8; p++) {
        int idx = tid + 256 * p;
        int rowj = idx >> 5, k4 = idx & 31;
        float4 v = *(const float4*)&Wout[(size_t)(col0 + rowj) * DD + k4 * 4];
        float* d = &ws[rowj * 130 + k4 * 4];
        d[0] = v.x; d[1] = v.y; d[2] = v.z; d[3] = v.w;
    }
    // gather tri rows from planar layout (coalesced per plane)
    #pragma unroll
    for (int p = 0; p < 32; p++) {
        int idx = tid + 256 * p;              // 8192 elements
        int rr = idx & 63, dd = idx >> 6;
        ys[rr * 130 + dd] = g_x[(size_t)dd * NROWS + row0 + rr];
    }
    __syncthreads();

    {   // LN2 per row
        int warp = tid >> 5, lane = tid & 31;
        float w4[4], b4[4];
        #pragma unroll
        for (int q = 0; q < 4; q++) { w4[q] = ln2w[lane * 4 + q]; b4[q] = ln2b[lane * 4 + q]; }
        #pragma unroll
        for (int rr = 0; rr < 8; rr++) {
            int lrow = warp * 8 + rr;
            float* row = &ys[lrow * 130 + lane * 4];
            float v0 = row[0], v1 = row[1], v2 = row[2], v3 = row[3];
            float s = v0 + v1 + v2 + v3;
            float q2 = v0 * v0 + v1 * v1 + v2 * v2 + v3 * v3;
            #pragma unroll
            for (int o = 16; o; o >>= 1) {
                s  += __shfl_xor_sync(0xffffffffu, s, o);
                q2 += __shfl_xor_sync(0xffffffffu, q2, o);
            }
            float mu = s * (1.0f / DD);
            float var = q2 * (1.0f / DD) - mu * mu;
            float rs = rsqrtf(var + 1e-5f);
            row[0] = (v0 - mu) * rs * w4[0] + b4[0];
            row[1] = (v1 - mu) * rs * w4[1] + b4[1];
            row[2] = (v2 - mu) * rs * w4[2] + b4[2];
            row[3] = (v3 - mu) * rs * w4[3] + b4[3];
        }
    }
    __syncthreads();

    const int tm = tid >> 4, tx = tid & 15;
    ull acc[4][4];
    #pragma unroll
    for (int a = 0; a < 4; a++)
        #pragma unroll
        for (int c = 0; c < 4; c++) acc[a][c] = 0ull;

    #pragma unroll 4
    for (int k2 = 0; k2 < 64; k2++) {
        ull yp[4], wp[4];
        #pragma unroll
        for (int a = 0; a < 4; a++) yp[a] = *(const ull*)&ys[(tm + 16 * a) * 130 + 2 * k2];
        #pragma unroll
        for (int c = 0; c < 4; c++) wp[c] = *(const ull*)&ws[(tx + 16 * c) * 130 + 2 * k2];
        #pragma unroll
        for (int a = 0; a < 4; a++)
            #pragma unroll
            for (int c = 0; c < 4; c++) acc[a][c] = ffma2(yp[a], wp[c], acc[a][c]);
    }

    #pragma unroll
    for (int a = 0; a < 4; a++) {
        int r = row0 + tm + 16 * a;
        size_t base = (size_t)r * DD;
        #pragma unroll
        for (int c = 0; c < 4; c++) {
            int col = col0 + tx + 16 * c;
            float lo, hi; unpk(acc[a][c], lo, hi);
            out[base + col] = g_og[base + col] * (lo + hi + bout[col]);
        }
    }
}

extern "C" void kernel_launch(void* const* d_in, const int* in_sizes, int n_in,
                              void* d_out, int out_size) {
    const float* edges = (const float*)d_in[0];
    const void*  mask  = d_in[1];
    const float* ln1w  = (const float*)d_in[2];
    const float* ln1b  = (const float*)d_in[3];
    const float* Wfg   = (const float*)d_in[4];
    const float* bfg   = (const float*)d_in[5];
    const float* Wgo   = (const float*)d_in[6];
    const float* bgo   = (const float*)d_in[7];
    const float* ln2w  = (const float*)d_in[8];
    const float* ln2b  = (const float*)d_in[9];
    const float* Wout  = (const float*)d_in[10];
    const float* bout  = (const float*)d_in[11];
    float* out = (float*)d_out;

    cudaFuncSetAttribute(k_fg,  cudaFuncAttributeMaxDynamicSharedMemorySize, 99840);
    cudaFuncSetAttribute(k_tri, cudaFuncAttributeMaxDynamicSharedMemorySize, TRI_SMEM);
    cudaFuncSetAttribute(k_out, cudaFuncAttributeMaxDynamicSharedMemorySize, 66560);

    k_detect<<<1, 256>>>((const unsigned int*)mask);
    k_ln<<<NROWS, 128>>>(edges, ln1w, ln1b);
    k_fg<<<dim3(10, NROWS / 128), 256, 99840>>>(mask, Wfg, bfg, Wgo, bgo);
    k_tri<<<dim3(NN / 128, NN / 128, DD), 256, TRI_SMEM>>>();
    k_out<<<dim3(2, NROWS / 64), 256, 66560>>>(ln2w, ln2b, Wout, bout, out);
}

// round 12
// speedup vs baseline: 1.9941x; 1.3501x over previous
#include <cuda_runtime.h>
#include <cuda_bf16.h>
#include <math.h>
#include <stdint.h>

#define NN 512
#define DD 128
#define NROWS (NN*NN)
typedef unsigned long long ull;

// ---- scratch (device globals; allocation is forbidden) ----
__device__ float g_x[NROWS*DD];                 // tri planar [d][i*NN+j]
__device__ float g_og[NROWS*DD];                // out_gate [row][d]
__device__ __nv_bfloat16 g_xhi[(size_t)NROWS*DD];   // normed x hi [row][d]
__device__ __nv_bfloat16 g_xlo[(size_t)NROWS*DD];   // normed x lo [row][d]
__device__ __nv_bfloat16 g_to_hi[(size_t)DD*NROWS];
__device__ __nv_bfloat16 g_to_lo[(size_t)DD*NROWS];
__device__ __nv_bfloat16 g_fr_hi[(size_t)DD*NROWS];
__device__ __nv_bfloat16 g_fr_lo[(size_t)DD*NROWS];
__device__ int g_mode;

static __device__ __forceinline__ ull ffma2(ull a, ull b, ull c) {
    ull d; asm("fma.rn.f32x2 %0, %1, %2, %3;" : "=l"(d) : "l"(a), "l"(b), "l"(c)); return d;
}
static __device__ __forceinline__ void unpk(ull v, float& a, float& b) {
    asm("mov.b64 {%0, %1}, %2;" : "=f"(a), "=f"(b) : "l"(v));
}
static __device__ __forceinline__ float sigm(float x) { return 1.0f / (1.0f + __expf(-x)); }

static __device__ __forceinline__ uint32_t smem_u32(const void* p) {
    uint32_t a;
    asm("{ .reg .u64 t; cvta.to.shared.u64 t, %1; cvt.u32.u64 %0, t; }" : "=r"(a) : "l"(p));
    return a;
}
static __device__ __forceinline__ uint32_t pkbf(__nv_bfloat16 a, __nv_bfloat16 b) {
    __nv_bfloat162 t; t.x = a; t.y = b;
    return *(uint32_t*)&t;
}

// ---- baseline-PTX tensor ops (no sm_103a-gated instructions) ----
static __device__ __forceinline__ void ldsm_x4(uint32_t* r, uint32_t addr) {
    asm volatile("ldmatrix.sync.aligned.m8n8.x4.shared.b16 {%0,%1,%2,%3}, [%4];"
                 : "=r"(r[0]), "=r"(r[1]), "=r"(r[2]), "=r"(r[3]) : "r"(addr));
}
static __device__ __forceinline__ void ldsm_x2(uint32_t* r, uint32_t addr) {
    asm volatile("ldmatrix.sync.aligned.m8n8.x2.shared.b16 {%0,%1}, [%2];"
                 : "=r"(r[0]), "=r"(r[1]) : "r"(addr));
}
static __device__ __forceinline__ void mma_bf16(float* c, const uint32_t* a, const uint32_t* b) {
    asm volatile("mma.sync.aligned.m16n8k16.row.col.f32.bf16.bf16.f32 "
                 "{%0,%1,%2,%3}, {%4,%5,%6,%7}, {%8,%9}, {%0,%1,%2,%3};"
                 : "+f"(c[0]), "+f"(c[1]), "+f"(c[2]), "+f"(c[3])
                 : "r"(a[0]), "r"(a[1]), "r"(a[2]), "r"(a[3]), "r"(b[0]), "r"(b[1]));
}

// ---- mask dtype detection: 0=u8, 1=i32, 2=f32, 3=bf16 ----
__global__ void k_detect(const unsigned int* __restrict__ m) {
    __shared__ int c[4];
    int t = threadIdx.x;
    if (t < 4) c[t] = 0;
    __syncthreads();
    int cb = 0, cf = 0, ci = 0, co = 0;
    for (int i = t; i < 65536; i += 256) {
        unsigned v = m[i];
        if (!v) continue;
        if (v == 0x3F803F80u || v == 0x00003F80u) cb++;
        else if (v == 0x3F800000u) cf++;
        else if (v == 1u) ci++;
        else co++;
    }
    atomicAdd(&c[0], cb); atomicAdd(&c[1], cf); atomicAdd(&c[2], ci); atomicAdd(&c[3], co);
    __syncthreads();
    if (t == 0) {
        int mode;
        if      (c[0] > 64) mode = 3;
        else if (c[3] > 64) mode = 0;
        else if (c[1] > 64) mode = 2;
        else                mode = 1;
        g_mode = mode;
    }
}
static __device__ __forceinline__ float mask_at(const void* m, int mode, int idx) {
    if (mode == 2) return ((const float*)m)[idx] != 0.0f ? 1.0f : 0.0f;
    if (mode == 0) return ((const unsigned char*)m)[idx] ? 1.0f : 0.0f;
    if (mode == 1) return ((const int*)m)[idx] ? 1.0f : 0.0f;
    return ((const unsigned short*)m)[idx] ? 1.0f : 0.0f;
}

// ---- Stage 1: LN1 over d -> bf16 hi/lo split, row-major ----
__global__ __launch_bounds__(128) void k_ln(const float* __restrict__ edges,
                                            const float* __restrict__ w,
                                            const float* __restrict__ b) {
    __shared__ float sA[4], sB[4];
    int t = threadIdx.x;
    int r = blockIdx.x;
    float e = edges[(size_t)r * DD + t];
    float s = e, q = e * e;
    #pragma unroll
    for (int o = 16; o; o >>= 1) {
        s += __shfl_xor_sync(0xffffffffu, s, o);
        q += __shfl_xor_sync(0xffffffffu, q, o);
    }
    if ((t & 31) == 0) { sA[t >> 5] = s; sB[t >> 5] = q; }
    __syncthreads();
    s = sA[0] + sA[1] + sA[2] + sA[3];
    q = sB[0] + sB[1] + sB[2] + sB[3];
    float mu = s * (1.0f / DD);
    float var = q * (1.0f / DD) - mu * mu;
    float rs = rsqrtf(var + 1e-5f);
    float v = (e - mu) * rs * w[t] + b[t];
    __nv_bfloat16 h = __float2bfloat16(v);
    g_xhi[(size_t)r * DD + t] = h;
    g_xlo[(size_t)r * DD + t] = __float2bfloat16(v - __bfloat162float(h));
}

// ---- Stage 2: fused projection via HMMA ----
// grid.x 0..3: fg blocks (64 feat/gate pairs interleaved per block); 4: out_gate.
// BM=128 rows, BN=128 cols, K=128. smem: xh/xl 32KB each + wh/wl 32KB each = 128KB.
// Tiles stored as two [rows][64-bf16] swizzled halves (16KB each for x, 16KB for W).
#define FG_SMEM 131072
__global__ __launch_bounds__(256) void k_fg(const void*  __restrict__ mask,
                                            const float* __restrict__ Wfg,
                                            const float* __restrict__ bfg,
                                            const float* __restrict__ Wgo,
                                            const float* __restrict__ bgo) {
    extern __shared__ char smc[];
    const uint32_t sb = smem_u32(smc);
    const int tid = threadIdx.x;
    const int wid = tid >> 5, lane = tid & 31;
    const int nt = blockIdx.x;
    const int row0 = blockIdx.y * 128;
    const int mode = g_mode;
    const int wm = wid >> 1, wn = wid & 1;   // 4 m-warps x 2 n-warps

    // load x hi/lo tiles (bf16 row-major -> swizzled halves)
    #pragma unroll
    for (int s = 0; s < 2; s++) {
        const __nv_bfloat16* src = s ? g_xlo : g_xhi;
        char* dstb = smc + s * 32768;
        #pragma unroll
        for (int p = 0; p < 8; p++) {
            int idx = tid + 256 * p;            // 0..2047 uint4
            int row = idx >> 4;
            int u = idx & 15;
            int h = u >> 3, c16 = u & 7;
            uint4 v = *(const uint4*)&src[(size_t)(row0 + row) * DD + h * 64 + c16 * 8];
            uint32_t off = (row << 7) + (c16 << 4);
            off ^= (off >> 3) & 0x70;
            *(uint4*)(dstb + h * 16384 + off) = v;
        }
    }
    // load + split W (fp32 -> bf16 hi/lo). fg blocks: row 2r=feat nt*64+r, 2r+1=gate 256+nt*64+r.
    #pragma unroll
    for (int p = 0; p < 16; p++) {
        int idx = tid + 256 * p;                // 0..4095 float4
        int j = idx >> 5;                       // B row 0..127
        int c4 = idx & 31;                      // float4 idx (k = c4*4)
        const float* src;
        if (nt < 4) {
            int pr = j >> 1;
            int e = (j & 1) ? (256 + nt * 64 + pr) : (nt * 64 + pr);
            src = Wfg + (size_t)e * DD;
        } else {
            src = Wgo + (size_t)j * DD;
        }
        float4 v = *(const float4*)(src + c4 * 4);
        __nv_bfloat16 h0 = __float2bfloat16(v.x), h1 = __float2bfloat16(v.y);
        __nv_bfloat16 h2 = __float2bfloat16(v.z), h3 = __float2bfloat16(v.w);
        __nv_bfloat16 l0 = __float2bfloat16(v.x - __bfloat162float(h0));
        __nv_bfloat16 l1 = __float2bfloat16(v.y - __bfloat162float(h1));
        __nv_bfloat16 l2 = __float2bfloat16(v.z - __bfloat162float(h2));
        __nv_bfloat16 l3 = __float2bfloat16(v.w - __bfloat162float(h3));
        int hh = c4 >> 4;
        int c16 = (c4 & 15) >> 1;
        int sub = (c4 & 1) * 8;
        uint32_t off = (j << 7) + (c16 << 4);
        off ^= (off >> 3) & 0x70;
        *(uint2*)(smc + 65536 + hh * 16384 + off + sub) = make_uint2(pkbf(h0, h1), pkbf(h2, h3));
        *(uint2*)(smc + 98304 + hh * 16384 + off + sub) = make_uint2(pkbf(l0, l1), pkbf(l2, l3));
    }
    __syncthreads();

    float acc[2][8][4];
    #pragma unroll
    for (int mt = 0; mt < 2; mt++)
        #pragma unroll
        for (int nf = 0; nf < 8; nf++)
            #pragma unroll
            for (int q = 0; q < 4; q++) acc[mt][nf][q] = 0.0f;

    #pragma unroll
    for (int ks = 0; ks < 8; ks++) {
        int h = ks >> 2, kk = ks & 3;
        uint32_t b_hi[8][2], b_lo[8][2];
        #pragma unroll
        for (int nf = 0; nf < 8; nf++) {
            uint32_t off = ((uint32_t)(wn * 64 + nf * 8 + (lane & 7)) << 7)
                         + ((uint32_t)kk << 5) + (((uint32_t)(lane >> 3) & 1) << 4);
            off ^= (off >> 3) & 0x70;
            ldsm_x2(b_hi[nf], sb + 65536 + h * 16384 + off);
            ldsm_x2(b_lo[nf], sb + 98304 + h * 16384 + off);
        }
        #pragma unroll
        for (int mt = 0; mt < 2; mt++) {
            uint32_t a_hi[4], a_lo[4];
            uint32_t off = ((uint32_t)(wm * 32 + mt * 16 + (lane & 15)) << 7)
                         + ((uint32_t)kk << 5) + ((uint32_t)(lane >> 4) << 4);
            off ^= (off >> 3) & 0x70;
            ldsm_x4(a_hi, sb + h * 16384 + off);
            ldsm_x4(a_lo, sb + 32768 + h * 16384 + off);
            #pragma unroll
            for (int nf = 0; nf < 8; nf++) {
                mma_bf16(acc[mt][nf], a_hi, b_hi[nf]);
                mma_bf16(acc[mt][nf], a_hi, b_lo[nf]);
                mma_bf16(acc[mt][nf], a_lo, b_hi[nf]);
            }
        }
    }

    if (nt < 4) {
        #pragma unroll
        for (int nf = 0; nf < 8; nf++) {
            int f = nt * 64 + wn * 32 + nf * 4 + (lane & 3);
            float bf = bfg[f], bg = bfg[256 + f];
            __nv_bfloat16* ph; __nv_bfloat16* pl;
            if (f < 128) { ph = g_to_hi + (size_t)f * NROWS;         pl = g_to_lo + (size_t)f * NROWS; }
            else         { ph = g_fr_hi + (size_t)(f - 128) * NROWS; pl = g_fr_lo + (size_t)(f - 128) * NROWS; }
            #pragma unroll
            for (int mt = 0; mt < 2; mt++) {
                int r = row0 + wm * 32 + mt * 16 + (lane >> 2);
                float mv0 = mask_at(mask, mode, r);
                float mv1 = mask_at(mask, mode, r + 8);
                float v0 = (acc[mt][nf][0] + bf) * sigm(acc[mt][nf][1] + bg) * mv0;
                float v1 = (acc[mt][nf][2] + bf) * sigm(acc[mt][nf][3] + bg) * mv1;
                __nv_bfloat16 h0 = __float2bfloat16(v0);
                __nv_bfloat16 l0 = __float2bfloat16(v0 - __bfloat162float(h0));
                __nv_bfloat16 h1 = __float2bfloat16(v1);
                __nv_bfloat16 l1 = __float2bfloat16(v1 - __bfloat162float(h1));
                ph[r] = h0;     pl[r] = l0;
                ph[r + 8] = h1; pl[r + 8] = l1;
            }
        }
    } else {
        #pragma unroll
        for (int nf = 0; nf < 8; nf++) {
            int e = wn * 64 + nf * 8 + (lane & 3) * 2;
            float b0 = bgo[e], b1 = bgo[e + 1];
            #pragma unroll
            for (int mt = 0; mt < 2; mt++) {
                int r = row0 + wm * 32 + mt * 16 + (lane >> 2);
                float mv0 = mask_at(mask, mode, r);
                float mv1 = mask_at(mask, mode, r + 8);
                *(float2*)&g_og[(size_t)r * DD + e] =
                    make_float2(sigm(acc[mt][nf][0] + b0) * mv0, sigm(acc[mt][nf][1] + b1) * mv0);
                *(float2*)&g_og[(size_t)(r + 8) * DD + e] =
                    make_float2(sigm(acc[mt][nf][2] + b0) * mv1, sigm(acc[mt][nf][3] + b1) * mv1);
            }
        }
    }
}

// ---- Stage 3: tri via HMMA (restructured for 2 CTAs/SM) ----
#define TRI_SMEM 65536
__global__ __launch_bounds__(256, 2) void k_tri() {
    extern __shared__ char smc[];
    const uint32_t sb = smem_u32(smc);
    const int tid = threadIdx.x;
    const int wid = tid >> 5, lane = tid & 31;
    const int j0 = blockIdx.x * 128, i0 = blockIdx.y * 128, d = blockIdx.z;
    const int wm = wid >> 2, wn = wid & 3;

    float acc[4][4][4];
    #pragma unroll
    for (int mt = 0; mt < 4; mt++)
        #pragma unroll
        for (int nt = 0; nt < 4; nt++)
            #pragma unroll
            for (int q = 0; q < 4; q++) acc[mt][nt][q] = 0.0f;

    const __nv_bfloat16* srcs[4] = {
        g_to_hi + (size_t)d * NROWS + (size_t)i0 * NN,
        g_to_lo + (size_t)d * NROWS + (size_t)i0 * NN,
        g_fr_hi + (size_t)d * NROWS + (size_t)j0 * NN,
        g_fr_lo + (size_t)d * NROWS + (size_t)j0 * NN
    };

    for (int kp = 0; kp < 8; kp++) {
        int k0 = kp * 64;
        #pragma unroll
        for (int t = 0; t < 4; t++) {
            const __nv_bfloat16* s = srcs[t] + k0;
            char* dst = smc + t * 16384;
            #pragma unroll
            for (int p = 0; p < 4; p++) {
                int idx = tid + 256 * p;
                int row = idx >> 3, c = idx & 7;
                uint4 v = *(const uint4*)(s + (size_t)row * NN + c * 8);
                uint32_t off = (row << 7) + (c << 4);
                off ^= (off >> 3) & 0x70;
                *(uint4*)(dst + off) = v;
            }
        }
        __syncthreads();

        #pragma unroll
        for (int ks = 0; ks < 4; ks++) {
            uint32_t b_hi[4][2], b_lo[4][2];
            #pragma unroll
            for (int nt = 0; nt < 4; nt++) {
                uint32_t off = (uint32_t)((wn * 32 + nt * 8 + (lane & 7)) << 7)
                             + (uint32_t)(ks * 32) + ((uint32_t)((lane >> 3) & 1) << 4);
                off ^= (off >> 3) & 0x70;
                ldsm_x2(b_hi[nt], sb + 32768 + off);
                ldsm_x2(b_lo[nt], sb + 49152 + off);
            }
            #pragma unroll
            for (int mt = 0; mt < 4; mt++) {
                uint32_t a_hi[4], a_lo[4];
                uint32_t off = (uint32_t)((wm * 64 + mt * 16 + (lane & 15)) << 7)
                             + (uint32_t)(ks * 32) + ((uint32_t)(lane >> 4) << 4);
                off ^= (off >> 3) & 0x70;
                ldsm_x4(a_hi, sb + off);
                ldsm_x4(a_lo, sb + 16384 + off);
                #pragma unroll
                for (int nt = 0; nt < 4; nt++) {
                    mma_bf16(acc[mt][nt], a_hi, b_hi[nt]);
                    mma_bf16(acc[mt][nt], a_hi, b_lo[nt]);
                    mma_bf16(acc[mt][nt], a_lo, b_hi[nt]);
                }
            }
        }
        __syncthreads();
    }

    #pragma unroll
    for (int mt = 0; mt < 4; mt++) {
        int i = i0 + wm * 64 + mt * 16 + (lane >> 2);
        #pragma unroll
        for (int nt = 0; nt < 4; nt++) {
            int j = j0 + wn * 32 + nt * 8 + (lane & 3) * 2;
            size_t base = (size_t)d * NROWS + (size_t)i * NN + j;
            *(float2*)&g_x[base]          = make_float2(acc[mt][nt][0], acc[mt][nt][1]);
            *(float2*)&g_x[base + 8 * NN] = make_float2(acc[mt][nt][2], acc[mt][nt][3]);
        }
    }
}

// ---- Stage 4: LN2(tri planar) @ W_out^T + b_out, times out_gate ----
__global__ __launch_bounds__(256) void k_out(const float* __restrict__ ln2w,
                                             const float* __restrict__ ln2b,
                                             const float* __restrict__ Wout,
                                             const float* __restrict__ bout,
                                             float* __restrict__ out) {
    extern __shared__ float dsm[];
    float* ys = dsm;              // [64][130]
    float* ws = dsm + 64 * 130;   // [64][130]
    const int tid = threadIdx.x;
    const int col0 = blockIdx.x * 64;
    const int row0 = blockIdx.y * 64;

    #pragma unroll
    for (int p = 0; p < 8; p++) {
        int idx = tid + 256 * p;
        int rowj = idx >> 5, k4 = idx & 31;
        float4 v = *(const float4*)&Wout[(size_t)(col0 + rowj) * DD + k4 * 4];
        float* d = &ws[rowj * 130 + k4 * 4];
        d[0] = v.x; d[1] = v.y; d[2] = v.z; d[3] = v.w;
    }
    #pragma unroll
    for (int p = 0; p < 32; p++) {
        int idx = tid + 256 * p;
        int rr = idx & 63, dd = idx >> 6;
        ys[rr * 130 + dd] = g_x[(size_t)dd * NROWS + row0 + rr];
    }
    __syncthreads();

    {
        int warp = tid >> 5, lane = tid & 31;
        float w4[4], b4[4];
        #pragma unroll
        for (int q = 0; q < 4; q++) { w4[q] = ln2w[lane * 4 + q]; b4[q] = ln2b[lane * 4 + q]; }
        #pragma unroll
        for (int rr = 0; rr < 8; rr++) {
            int lrow = warp * 8 + rr;
            float* row = &ys[lrow * 130 + lane * 4];
            float v0 = row[0], v1 = row[1], v2 = row[2], v3 = row[3];
            float s = v0 + v1 + v2 + v3;
            float q2 = v0 * v0 + v1 * v1 + v2 * v2 + v3 * v3;
            #pragma unroll
            for (int o = 16; o; o >>= 1) {
                s  += __shfl_xor_sync(0xffffffffu, s, o);
                q2 += __shfl_xor_sync(0xffffffffu, q2, o);
            }
            float mu = s * (1.0f / DD);
            float var = q2 * (1.0f / DD) - mu * mu;
            float rs = rsqrtf(var + 1e-5f);
            row[0] = (v0 - mu) * rs * w4[0] + b4[0];
            row[1] = (v1 - mu) * rs * w4[1] + b4[1];
            row[2] = (v2 - mu) * rs * w4[2] + b4[2];
            row[3] = (v3 - mu) * rs * w4[3] + b4[3];
        }
    }
    __syncthreads();

    const int tm = tid >> 4, tx = tid & 15;
    ull acc[4][4];
    #pragma unroll
    for (int a = 0; a < 4; a++)
        #pragma unroll
        for (int c = 0; c < 4; c++) acc[a][c] = 0ull;

    #pragma unroll 4
    for (int k2 = 0; k2 < 64; k2++) {
        ull yp[4], wp[4];
        #pragma unroll
        for (int a = 0; a < 4; a++) yp[a] = *(const ull*)&ys[(tm + 16 * a) * 130 + 2 * k2];
        #pragma unroll
        for (int c = 0; c < 4; c++) wp[c] = *(const ull*)&ws[(tx + 16 * c) * 130 + 2 * k2];
        #pragma unroll
        for (int a = 0; a < 4; a++)
            #pragma unroll
            for (int c = 0; c < 4; c++) acc[a][c] = ffma2(yp[a], wp[c], acc[a][c]);
    }

    #pragma unroll
    for (int a = 0; a < 4; a++) {
        int r = row0 + tm + 16 * a;
        size_t base = (size_t)r * DD;
        #pragma unroll
        for (int c = 0; c < 4; c++) {
            int col = col0 + tx + 16 * c;
            float lo, hi; unpk(acc[a][c], lo, hi);
            out[base + col] = g_og[base + col] * (lo + hi + bout[col]);
        }
    }
}

extern "C" void kernel_launch(void* const* d_in, const int* in_sizes, int n_in,
                              void* d_out, int out_size) {
    const float* edges = (const float*)d_in[0];
    const void*  mask  = d_in[1];
    const float* ln1w  = (const float*)d_in[2];
    const float* ln1b  = (const float*)d_in[3];
    const float* Wfg   = (const float*)d_in[4];
    const float* bfg   = (const float*)d_in[5];
    const float* Wgo   = (const float*)d_in[6];
    const float* bgo   = (const float*)d_in[7];
    const float* ln2w  = (const float*)d_in[8];
    const float* ln2b  = (const float*)d_in[9];
    const float* Wout  = (const float*)d_in[10];
    const float* bout  = (const float*)d_in[11];
    float* out = (float*)d_out;

    cudaFuncSetAttribute(k_fg,  cudaFuncAttributeMaxDynamicSharedMemorySize, FG_SMEM);
    cudaFuncSetAttribute(k_tri, cudaFuncAttributeMaxDynamicSharedMemorySize, TRI_SMEM);
    cudaFuncSetAttribute(k_out, cudaFuncAttributeMaxDynamicSharedMemorySize, 66560);

    k_detect<<<1, 256>>>((const unsigned int*)mask);
    k_ln<<<NROWS, 128>>>(edges, ln1w, ln1b);
    k_fg<<<dim3(5, NROWS / 128), 256, FG_SMEM>>>(mask, Wfg, bfg, Wgo, bgo);
    k_tri<<<dim3(NN / 128, NN / 128, DD), 256, TRI_SMEM>>>();
    k_out<<<dim3(2, NROWS / 64), 256, 66560>>>(ln2w, ln2b, Wout, bout, out);
}

// round 13
// speedup vs baseline: 2.0851x; 1.0456x over previous
#include <cuda_runtime.h>
#include <cuda_bf16.h>
#include <math.h>
#include <stdint.h>

#define NN 512
#define DD 128
#define NROWS (NN*NN)
typedef unsigned long long ull;

// ---- scratch (device globals; allocation is forbidden) ----
__device__ float g_x[NROWS*DD];                 // tri planar [d][i*NN+j]
__device__ float g_og[NROWS*DD];                // out_gate [row][d]
__device__ __nv_bfloat16 g_xhi[(size_t)NROWS*DD];   // normed x hi [row][d]
__device__ __nv_bfloat16 g_xlo[(size_t)NROWS*DD];   // normed x lo [row][d]
__device__ __nv_bfloat16 g_to_hi[(size_t)DD*NROWS];
__device__ __nv_bfloat16 g_to_lo[(size_t)DD*NROWS];
__device__ __nv_bfloat16 g_fr_hi[(size_t)DD*NROWS];
__device__ __nv_bfloat16 g_fr_lo[(size_t)DD*NROWS];
__device__ int g_mode;

static __device__ __forceinline__ float sigm(float x) { return 1.0f / (1.0f + __expf(-x)); }

static __device__ __forceinline__ uint32_t smem_u32(const void* p) {
    uint32_t a;
    asm("{ .reg .u64 t; cvta.to.shared.u64 t, %1; cvt.u32.u64 %0, t; }" : "=r"(a) : "l"(p));
    return a;
}
static __device__ __forceinline__ uint32_t pkbf(__nv_bfloat16 a, __nv_bfloat16 b) {
    __nv_bfloat162 t; t.x = a; t.y = b;
    return *(uint32_t*)&t;
}

// ---- baseline-PTX tensor + async ops (no sm_103a-gated instructions) ----
static __device__ __forceinline__ void ldsm_x4(uint32_t* r, uint32_t addr) {
    asm volatile("ldmatrix.sync.aligned.m8n8.x4.shared.b16 {%0,%1,%2,%3}, [%4];"
                 : "=r"(r[0]), "=r"(r[1]), "=r"(r[2]), "=r"(r[3]) : "r"(addr));
}
static __device__ __forceinline__ void ldsm_x2(uint32_t* r, uint32_t addr) {
    asm volatile("ldmatrix.sync.aligned.m8n8.x2.shared.b16 {%0,%1}, [%2];"
                 : "=r"(r[0]), "=r"(r[1]) : "r"(addr));
}
static __device__ __forceinline__ void mma_bf16(float* c, const uint32_t* a, const uint32_t* b) {
    asm volatile("mma.sync.aligned.m16n8k16.row.col.f32.bf16.bf16.f32 "
                 "{%0,%1,%2,%3}, {%4,%5,%6,%7}, {%8,%9}, {%0,%1,%2,%3};"
                 : "+f"(c[0]), "+f"(c[1]), "+f"(c[2]), "+f"(c[3])
                 : "r"(a[0]), "r"(a[1]), "r"(a[2]), "r"(a[3]), "r"(b[0]), "r"(b[1]));
}
static __device__ __forceinline__ void cp16(uint32_t smem, const void* gmem) {
    asm volatile("cp.async.cg.shared.global [%0], [%1], 16;" :: "r"(smem), "l"(gmem));
}
#define CP_COMMIT() asm volatile("cp.async.commit_group;" ::: "memory")

// ---- mask dtype detection: 0=u8, 1=i32, 2=f32, 3=bf16 ----
__global__ void k_detect(const unsigned int* __restrict__ m) {
    __shared__ int c[4];
    int t = threadIdx.x;
    if (t < 4) c[t] = 0;
    __syncthreads();
    int cb = 0, cf = 0, ci = 0, co = 0;
    for (int i = t; i < 65536; i += 256) {
        unsigned v = m[i];
        if (!v) continue;
        if (v == 0x3F803F80u || v == 0x00003F80u) cb++;
        else if (v == 0x3F800000u) cf++;
        else if (v == 1u) ci++;
        else co++;
    }
    atomicAdd(&c[0], cb); atomicAdd(&c[1], cf); atomicAdd(&c[2], ci); atomicAdd(&c[3], co);
    __syncthreads();
    if (t == 0) {
        int mode;
        if      (c[0] > 64) mode = 3;
        else if (c[3] > 64) mode = 0;
        else if (c[1] > 64) mode = 2;
        else                mode = 1;
        g_mode = mode;
    }
}
static __device__ __forceinline__ float mask_at(const void* m, int mode, int idx) {
    if (mode == 2) return ((const float*)m)[idx] != 0.0f ? 1.0f : 0.0f;
    if (mode == 0) return ((const unsigned char*)m)[idx] ? 1.0f : 0.0f;
    if (mode == 1) return ((const int*)m)[idx] ? 1.0f : 0.0f;
    return ((const unsigned short*)m)[idx] ? 1.0f : 0.0f;
}

// ---- Stage 1: LN1 over d -> bf16 hi/lo split, row-major ----
__global__ __launch_bounds__(128) void k_ln(const float* __restrict__ edges,
                                            const float* __restrict__ w,
                                            const float* __restrict__ b) {
    __shared__ float sA[4], sB[4];
    int t = threadIdx.x;
    int r = blockIdx.x;
    float e = edges[(size_t)r * DD + t];
    float s = e, q = e * e;
    #pragma unroll
    for (int o = 16; o; o >>= 1) {
        s += __shfl_xor_sync(0xffffffffu, s, o);
        q += __shfl_xor_sync(0xffffffffu, q, o);
    }
    if ((t & 31) == 0) { sA[t >> 5] = s; sB[t >> 5] = q; }
    __syncthreads();
    s = sA[0] + sA[1] + sA[2] + sA[3];
    q = sB[0] + sB[1] + sB[2] + sB[3];
    float mu = s * (1.0f / DD);
    float var = q * (1.0f / DD) - mu * mu;
    float rs = rsqrtf(var + 1e-5f);
    float v = (e - mu) * rs * w[t] + b[t];
    __nv_bfloat16 h = __float2bfloat16(v);
    g_xhi[(size_t)r * DD + t] = h;
    g_xlo[(size_t)r * DD + t] = __float2bfloat16(v - __bfloat162float(h));
}

// ---- Stage 2: fused projection via HMMA ----
// grid.x 0..3: fg blocks (64 feat/gate pairs interleaved per block); 4: out_gate.
#define FG_SMEM 131072
__global__ __launch_bounds__(256) void k_fg(const void*  __restrict__ mask,
                                            const float* __restrict__ Wfg,
                                            const float* __restrict__ bfg,
                                            const float* __restrict__ Wgo,
                                            const float* __restrict__ bgo) {
    extern __shared__ char smc[];
    const uint32_t sb = smem_u32(smc);
    const int tid = threadIdx.x;
    const int wid = tid >> 5, lane = tid & 31;
    const int nt = blockIdx.x;
    const int row0 = blockIdx.y * 128;
    const int mode = g_mode;
    const int wm = wid >> 1, wn = wid & 1;

    #pragma unroll
    for (int s = 0; s < 2; s++) {
        const __nv_bfloat16* src = s ? g_xlo : g_xhi;
        char* dstb = smc + s * 32768;
        #pragma unroll
        for (int p = 0; p < 8; p++) {
            int idx = tid + 256 * p;
            int row = idx >> 4;
            int u = idx & 15;
            int h = u >> 3, c16 = u & 7;
            uint4 v = *(const uint4*)&src[(size_t)(row0 + row) * DD + h * 64 + c16 * 8];
            uint32_t off = (row << 7) + (c16 << 4);
            off ^= (off >> 3) & 0x70;
            *(uint4*)(dstb + h * 16384 + off) = v;
        }
    }
    #pragma unroll
    for (int p = 0; p < 16; p++) {
        int idx = tid + 256 * p;
        int j = idx >> 5;
        int c4 = idx & 31;
        const float* src;
        if (nt < 4) {
            int pr = j >> 1;
            int e = (j & 1) ? (256 + nt * 64 + pr) : (nt * 64 + pr);
            src = Wfg + (size_t)e * DD;
        } else {
            src = Wgo + (size_t)j * DD;
        }
        float4 v = *(const float4*)(src + c4 * 4);
        __nv_bfloat16 h0 = __float2bfloat16(v.x), h1 = __float2bfloat16(v.y);
        __nv_bfloat16 h2 = __float2bfloat16(v.z), h3 = __float2bfloat16(v.w);
        __nv_bfloat16 l0 = __float2bfloat16(v.x - __bfloat162float(h0));
        __nv_bfloat16 l1 = __float2bfloat16(v.y - __bfloat162float(h1));
        __nv_bfloat16 l2 = __float2bfloat16(v.z - __bfloat162float(h2));
        __nv_bfloat16 l3 = __float2bfloat16(v.w - __bfloat162float(h3));
        int hh = c4 >> 4;
        int c16 = (c4 & 15) >> 1;
        int sub = (c4 & 1) * 8;
        uint32_t off = (j << 7) + (c16 << 4);
        off ^= (off >> 3) & 0x70;
        *(uint2*)(smc + 65536 + hh * 16384 + off + sub) = make_uint2(pkbf(h0, h1), pkbf(h2, h3));
        *(uint2*)(smc + 98304 + hh * 16384 + off + sub) = make_uint2(pkbf(l0, l1), pkbf(l2, l3));
    }
    __syncthreads();

    float acc[2][8][4];
    #pragma unroll
    for (int mt = 0; mt < 2; mt++)
        #pragma unroll
        for (int nf = 0; nf < 8; nf++)
            #pragma unroll
            for (int q = 0; q < 4; q++) acc[mt][nf][q] = 0.0f;

    #pragma unroll
    for (int ks = 0; ks < 8; ks++) {
        int h = ks >> 2, kk = ks & 3;
        uint32_t b_hi[8][2], b_lo[8][2];
        #pragma unroll
        for (int nf = 0; nf < 8; nf++) {
            uint32_t off = ((uint32_t)(wn * 64 + nf * 8 + (lane & 7)) << 7)
                         + ((uint32_t)kk << 5) + (((uint32_t)(lane >> 3) & 1) << 4);
            off ^= (off >> 3) & 0x70;
            ldsm_x2(b_hi[nf], sb + 65536 + h * 16384 + off);
            ldsm_x2(b_lo[nf], sb + 98304 + h * 16384 + off);
        }
        #pragma unroll
        for (int mt = 0; mt < 2; mt++) {
            uint32_t a_hi[4], a_lo[4];
            uint32_t off = ((uint32_t)(wm * 32 + mt * 16 + (lane & 15)) << 7)
                         + ((uint32_t)kk << 5) + ((uint32_t)(lane >> 4) << 4);
            off ^= (off >> 3) & 0x70;
            ldsm_x4(a_hi, sb + h * 16384 + off);
            ldsm_x4(a_lo, sb + 32768 + h * 16384 + off);
            #pragma unroll
            for (int nf = 0; nf < 8; nf++) {
                mma_bf16(acc[mt][nf], a_hi, b_hi[nf]);
                mma_bf16(acc[mt][nf], a_hi, b_lo[nf]);
                mma_bf16(acc[mt][nf], a_lo, b_hi[nf]);
            }
        }
    }

    if (nt < 4) {
        #pragma unroll
        for (int nf = 0; nf < 8; nf++) {
            int f = nt * 64 + wn * 32 + nf * 4 + (lane & 3);
            float bf = bfg[f], bg = bfg[256 + f];
            __nv_bfloat16* ph; __nv_bfloat16* pl;
            if (f < 128) { ph = g_to_hi + (size_t)f * NROWS;         pl = g_to_lo + (size_t)f * NROWS; }
            else         { ph = g_fr_hi + (size_t)(f - 128) * NROWS; pl = g_fr_lo + (size_t)(f - 128) * NROWS; }
            #pragma unroll
            for (int mt = 0; mt < 2; mt++) {
                int r = row0 + wm * 32 + mt * 16 + (lane >> 2);
                float mv0 = mask_at(mask, mode, r);
                float mv1 = mask_at(mask, mode, r + 8);
                float v0 = (acc[mt][nf][0] + bf) * sigm(acc[mt][nf][1] + bg) * mv0;
                float v1 = (acc[mt][nf][2] + bf) * sigm(acc[mt][nf][3] + bg) * mv1;
                __nv_bfloat16 h0 = __float2bfloat16(v0);
                __nv_bfloat16 l0 = __float2bfloat16(v0 - __bfloat162float(h0));
                __nv_bfloat16 h1 = __float2bfloat16(v1);
                __nv_bfloat16 l1 = __float2bfloat16(v1 - __bfloat162float(h1));
                ph[r] = h0;     pl[r] = l0;
                ph[r + 8] = h1; pl[r + 8] = l1;
            }
        }
    } else {
        #pragma unroll
        for (int nf = 0; nf < 8; nf++) {
            int e = wn * 64 + nf * 8 + (lane & 3) * 2;
            float b0 = bgo[e], b1 = bgo[e + 1];
            #pragma unroll
            for (int mt = 0; mt < 2; mt++) {
                int r = row0 + wm * 32 + mt * 16 + (lane >> 2);
                float mv0 = mask_at(mask, mode, r);
                float mv1 = mask_at(mask, mode, r + 8);
                *(float2*)&g_og[(size_t)r * DD + e] =
                    make_float2(sigm(acc[mt][nf][0] + b0) * mv0, sigm(acc[mt][nf][1] + b1) * mv0);
                *(float2*)&g_og[(size_t)(r + 8) * DD + e] =
                    make_float2(sigm(acc[mt][nf][2] + b0) * mv1, sigm(acc[mt][nf][3] + b1) * mv1);
            }
        }
    }
}

// ---- Stage 3: tri via HMMA + cp.async double buffering ----
// K-slab 32: 4 tiles x (128 rows x 32 bf16 = 64B rows, line-parity swizzle) = 32KB/buffer.
#define TRI_SMEM 65536
static __device__ __forceinline__ uint32_t sw64(uint32_t row, uint32_t chunk) {
    return (row << 6) + (((chunk ^ (row >> 1)) & 3) << 4);
}
__global__ __launch_bounds__(256, 2) void k_tri() {
    extern __shared__ char smc[];
    const uint32_t sb = smem_u32(smc);
    const int tid = threadIdx.x;
    const int wid = tid >> 5, lane = tid & 31;
    const int j0 = blockIdx.x * 128, i0 = blockIdx.y * 128, d = blockIdx.z;
    const int wm = wid >> 2, wn = wid & 3;

    float acc[4][4][4];
    #pragma unroll
    for (int mt = 0; mt < 4; mt++)
        #pragma unroll
        for (int nt = 0; nt < 4; nt++)
            #pragma unroll
            for (int q = 0; q < 4; q++) acc[mt][nt][q] = 0.0f;

    const __nv_bfloat16* srcs[4] = {
        g_to_hi + (size_t)d * NROWS + (size_t)i0 * NN,
        g_to_lo + (size_t)d * NROWS + (size_t)i0 * NN,
        g_fr_hi + (size_t)d * NROWS + (size_t)j0 * NN,
        g_fr_lo + (size_t)d * NROWS + (size_t)j0 * NN
    };

    auto load_slab = [&](int kp, int buf) {
        uint32_t bb = sb + buf * 32768;
        #pragma unroll
        for (int p = 0; p < 8; p++) {
            int idx = tid + 256 * p;          // 0..2047
            int t = idx >> 9;
            int r = (idx >> 2) & 127;
            int c = idx & 3;
            cp16(bb + t * 8192 + sw64(r, c), srcs[t] + (size_t)r * NN + kp * 32 + c * 8);
        }
        CP_COMMIT();
    };

    load_slab(0, 0);
    for (int kp = 0; kp < 16; kp++) {
        if (kp < 15) {
            load_slab(kp + 1, (kp + 1) & 1);
            asm volatile("cp.async.wait_group 1;" ::: "memory");
        } else {
            asm volatile("cp.async.wait_group 0;" ::: "memory");
        }
        __syncthreads();

        uint32_t bb = sb + (kp & 1) * 32768;
        #pragma unroll
        for (int ks = 0; ks < 2; ks++) {
            uint32_t b_hi[4][2], b_lo[4][2];
            #pragma unroll
            for (int nt = 0; nt < 4; nt++) {
                uint32_t off = sw64((uint32_t)(wn * 32 + nt * 8 + (lane & 7)),
                                    (uint32_t)(ks * 2 + ((lane >> 3) & 1)));
                ldsm_x2(b_hi[nt], bb + 16384 + off);
                ldsm_x2(b_lo[nt], bb + 24576 + off);
            }
            #pragma unroll
            for (int mt = 0; mt < 4; mt++) {
                uint32_t a_hi[4], a_lo[4];
                uint32_t off = sw64((uint32_t)(wm * 64 + mt * 16 + (lane & 15)),
                                    (uint32_t)(ks * 2 + (lane >> 4)));
                ldsm_x4(a_hi, bb + off);
                ldsm_x4(a_lo, bb + 8192 + off);
                #pragma unroll
                for (int nt = 0; nt < 4; nt++) {
                    mma_bf16(acc[mt][nt], a_hi, b_hi[nt]);
                    mma_bf16(acc[mt][nt], a_hi, b_lo[nt]);
                    mma_bf16(acc[mt][nt], a_lo, b_hi[nt]);
                }
            }
        }
        __syncthreads();
    }

    #pragma unroll
    for (int mt = 0; mt < 4; mt++) {
        int i = i0 + wm * 64 + mt * 16 + (lane >> 2);
        #pragma unroll
        for (int nt = 0; nt < 4; nt++) {
            int j = j0 + wn * 32 + nt * 8 + (lane & 3) * 2;
            size_t base = (size_t)d * NROWS + (size_t)i * NN + j;
            *(float2*)&g_x[base]          = make_float2(acc[mt][nt][0], acc[mt][nt][1]);
            *(float2*)&g_x[base + 8 * NN] = make_float2(acc[mt][nt][2], acc[mt][nt][3]);
        }
    }
}

// ---- Stage 4: LN2(tri planar) -> bf16 split -> HMMA with W_out, times out_gate ----
// smem: A hi [0,32KB) (two 16KB halves), A lo [32KB,64KB), W hi [64KB,96KB),
//       W lo [96KB,128KB), fp32 staging ys[128][133] at 128KB.
#define OUT_SMEM (131072 + 128*133*4)
__global__ __launch_bounds__(256) void k_out(const float* __restrict__ ln2w,
                                             const float* __restrict__ ln2b,
                                             const float* __restrict__ Wout,
                                             const float* __restrict__ bout,
                                             float* __restrict__ out) {
    extern __shared__ char smc[];
    const uint32_t sb = smem_u32(smc);
    float* ys = (float*)(smc + 131072);     // [128][133]
    const int tid = threadIdx.x;
    const int wid = tid >> 5, lane = tid & 31;
    const int row0 = blockIdx.x * 128;
    const int wm = wid >> 1, wn = wid & 1;

    // W_out load + bf16 split
    #pragma unroll
    for (int p = 0; p < 16; p++) {
        int idx = tid + 256 * p;
        int j = idx >> 5;
        int c4 = idx & 31;
        float4 v = *(const float4*)(Wout + (size_t)j * DD + c4 * 4);
        __nv_bfloat16 h0 = __float2bfloat16(v.x), h1 = __float2bfloat16(v.y);
        __nv_bfloat16 h2 = __float2bfloat16(v.z), h3 = __float2bfloat16(v.w);
        __nv_bfloat16 l0 = __float2bfloat16(v.x - __bfloat162float(h0));
        __nv_bfloat16 l1 = __float2bfloat16(v.y - __bfloat162float(h1));
        __nv_bfloat16 l2 = __float2bfloat16(v.z - __bfloat162float(h2));
        __nv_bfloat16 l3 = __float2bfloat16(v.w - __bfloat162float(h3));
        int hh = c4 >> 4;
        int c16 = (c4 & 15) >> 1;
        int sub = (c4 & 1) * 8;
        uint32_t off = (j << 7) + (c16 << 4);
        off ^= (off >> 3) & 0x70;
        *(uint2*)(smc + 65536 + hh * 16384 + off + sub) = make_uint2(pkbf(h0, h1), pkbf(h2, h3));
        *(uint2*)(smc + 98304 + hh * 16384 + off + sub) = make_uint2(pkbf(l0, l1), pkbf(l2, l3));
    }
    // planar tri gather -> fp32 staging
    #pragma unroll 8
    for (int p = 0; p < 64; p++) {
        int idx = tid + 256 * p;            // 16384
        int row = idx & 127, dd = idx >> 7;
        ys[row * 133 + dd] = g_x[(size_t)dd * NROWS + row0 + row];
    }
    __syncthreads();

    // LN2 per row -> bf16 hi/lo into A region (warp handles 16 rows)
    {
        float w4[4], b4[4];
        #pragma unroll
        for (int q = 0; q < 4; q++) { w4[q] = ln2w[lane * 4 + q]; b4[q] = ln2b[lane * 4 + q]; }
        int dd = lane * 4;
        int hh = dd >> 6;
        uint32_t offb = (uint32_t)((dd & 63) * 2);
        #pragma unroll
        for (int rr = 0; rr < 16; rr++) {
            int row = wid * 16 + rr;
            float* yr = &ys[row * 133 + dd];
            float v0 = yr[0], v1 = yr[1], v2 = yr[2], v3 = yr[3];
            float s = v0 + v1 + v2 + v3;
            float q2 = v0 * v0 + v1 * v1 + v2 * v2 + v3 * v3;
            #pragma unroll
            for (int o = 16; o; o >>= 1) {
                s  += __shfl_xor_sync(0xffffffffu, s, o);
                q2 += __shfl_xor_sync(0xffffffffu, q2, o);
            }
            float mu = s * (1.0f / DD);
            float var = q2 * (1.0f / DD) - mu * mu;
            float rs = rsqrtf(var + 1e-5f);
            float n0 = (v0 - mu) * rs * w4[0] + b4[0];
            float n1 = (v1 - mu) * rs * w4[1] + b4[1];
            float n2 = (v2 - mu) * rs * w4[2] + b4[2];
            float n3 = (v3 - mu) * rs * w4[3] + b4[3];
            __nv_bfloat16 h0 = __float2bfloat16(n0), h1 = __float2bfloat16(n1);
            __nv_bfloat16 h2 = __float2bfloat16(n2), h3 = __float2bfloat16(n3);
            __nv_bfloat16 l0 = __float2bfloat16(n0 - __bfloat162float(h0));
            __nv_bfloat16 l1 = __float2bfloat16(n1 - __bfloat162float(h1));
            __nv_bfloat16 l2 = __float2bfloat16(n2 - __bfloat162float(h2));
            __nv_bfloat16 l3 = __float2bfloat16(n3 - __bfloat162float(h3));
            uint32_t off = ((uint32_t)row << 7) + offb;
            off ^= (off >> 3) & 0x70;
            *(uint2*)(smc + hh * 16384 + off)         = make_uint2(pkbf(h0, h1), pkbf(h2, h3));
            *(uint2*)(smc + 32768 + hh * 16384 + off) = make_uint2(pkbf(l0, l1), pkbf(l2, l3));
        }
    }
    __syncthreads();

    float acc[2][8][4];
    #pragma unroll
    for (int mt = 0; mt < 2; mt++)
        #pragma unroll
        for (int nf = 0; nf < 8; nf++)
            #pragma unroll
            for (int q = 0; q < 4; q++) acc[mt][nf][q] = 0.0f;

    #pragma unroll
    for (int ks = 0; ks < 8; ks++) {
        int h = ks >> 2, kk = ks & 3;
        uint32_t b_hi[8][2], b_lo[8][2];
        #pragma unroll
        for (int nf = 0; nf < 8; nf++) {
            uint32_t off = ((uint32_t)(wn * 64 + nf * 8 + (lane & 7)) << 7)
                         + ((uint32_t)kk << 5) + (((uint32_t)(lane >> 3) & 1) << 4);
            off ^= (off >> 3) & 0x70;
            ldsm_x2(b_hi[nf], sb + 65536 + h * 16384 + off);
            ldsm_x2(b_lo[nf], sb + 98304 + h * 16384 + off);
        }
        #pragma unroll
        for (int mt = 0; mt < 2; mt++) {
            uint32_t a_hi[4], a_lo[4];
            uint32_t off = ((uint32_t)(wm * 32 + mt * 16 + (lane & 15)) << 7)
                         + ((uint32_t)kk << 5) + ((uint32_t)(lane >> 4) << 4);
            off ^= (off >> 3) & 0x70;
            ldsm_x4(a_hi, sb + h * 16384 + off);
            ldsm_x4(a_lo, sb + 32768 + h * 16384 + off);
            #pragma unroll
            for (int nf = 0; nf < 8; nf++) {
                mma_bf16(acc[mt][nf], a_hi, b_hi[nf]);
                mma_bf16(acc[mt][nf], a_hi, b_lo[nf]);
                mma_bf16(acc[mt][nf], a_lo, b_hi[nf]);
            }
        }
    }

    #pragma unroll
    for (int nf = 0; nf < 8; nf++) {
        int col = wn * 64 + nf * 8 + (lane & 3) * 2;
        float b0 = bout[col], b1 = bout[col + 1];
        #pragma unroll
        for (int mt = 0; mt < 2; mt++) {
            int r = row0 + wm * 32 + mt * 16 + (lane >> 2);
            size_t base = (size_t)r * DD + col;
            float2 og0 = *(const float2*)&g_og[base];
            *(float2*)&out[base] = make_float2(og0.x * (acc[mt][nf][0] + b0),
                                               og0.y * (acc[mt][nf][1] + b1));
            float2 og1 = *(const float2*)&g_og[base + 8 * DD];
            *(float2*)&out[base + 8 * DD] = make_float2(og1.x * (acc[mt][nf][2] + b0),
                                                        og1.y * (acc[mt][nf][3] + b1));
        }
    }
}

extern "C" void kernel_launch(void* const* d_in, const int* in_sizes, int n_in,
                              void* d_out, int out_size) {
    const float* edges = (const float*)d_in[0];
    const void*  mask  = d_in[1];
    const float* ln1w  = (const float*)d_in[2];
    const float* ln1b  = (const float*)d_in[3];
    const float* Wfg   = (const float*)d_in[4];
    const float* bfg   = (const float*)d_in[5];
    const float* Wgo   = (const float*)d_in[6];
    const float* bgo   = (const float*)d_in[7];
    const float* ln2w  = (const float*)d_in[8];
    const float* ln2b  = (const float*)d_in[9];
    const float* Wout  = (const float*)d_in[10];
    const float* bout  = (const float*)d_in[11];
    float* out = (float*)d_out;

    cudaFuncSetAttribute(k_fg,  cudaFuncAttributeMaxDynamicSharedMemorySize, FG_SMEM);
    cudaFuncSetAttribute(k_tri, cudaFuncAttributeMaxDynamicSharedMemorySize, TRI_SMEM);
    cudaFuncSetAttribute(k_out, cudaFuncAttributeMaxDynamicSharedMemorySize, OUT_SMEM);

    k_detect<<<1, 256>>>((const unsigned int*)mask);
    k_ln<<<NROWS, 128>>>(edges, ln1w, ln1b);
    k_fg<<<dim3(5, NROWS / 128), 256, FG_SMEM>>>(mask, Wfg, bfg, Wgo, bgo);
    k_tri<<<dim3(NN / 128, NN / 128, DD), 256, TRI_SMEM>>>();
    k_out<<<NROWS / 128, 256, OUT_SMEM>>>(ln2w, ln2b, Wout, bout, out);
}

// round 15
// speedup vs baseline: 2.4050x; 1.1534x over previous
#include <cuda_runtime.h>
#include <cuda_bf16.h>
#include <math.h>
#include <stdint.h>

#define NN 512
#define DD 128
#define NROWS (NN*NN)
typedef unsigned long long ull;

// ---- scratch (device globals; allocation is forbidden) ----
__device__ float g_x[NROWS*DD];                 // tri planar [d][i*NN+j]
__device__ float g_og[NROWS*DD];                // out_gate [row][d]
__device__ __nv_bfloat16 g_xhi[(size_t)NROWS*DD];   // normed x hi [row][d]
__device__ __nv_bfloat16 g_xlo[(size_t)NROWS*DD];   // normed x lo [row][d]
__device__ __nv_bfloat16 g_to_hi[(size_t)DD*NROWS];
__device__ __nv_bfloat16 g_to_lo[(size_t)DD*NROWS];
__device__ __nv_bfloat16 g_fr_hi[(size_t)DD*NROWS];
__device__ __nv_bfloat16 g_fr_lo[(size_t)DD*NROWS];
// Pre-split, pre-swizzled W smem images: tiles 0..3 = fg pairs, 4 = go, 5 = Wout.
// Per tile: [hi half0 16KB][hi half1 16KB][lo half0 16KB][lo half1 16KB] = 64KB.
__device__ __align__(16) unsigned char g_wimg[6*65536];
__device__ int g_mode;

static __device__ __forceinline__ float sigm(float x) { return 1.0f / (1.0f + __expf(-x)); }

static __device__ __forceinline__ uint32_t smem_u32(const void* p) {
    uint32_t a;
    asm("{ .reg .u64 t; cvta.to.shared.u64 t, %1; cvt.u32.u64 %0, t; }" : "=r"(a) : "l"(p));
    return a;
}
static __device__ __forceinline__ uint32_t pkbf(__nv_bfloat16 a, __nv_bfloat16 b) {
    __nv_bfloat162 t; t.x = a; t.y = b;
    return *(uint32_t*)&t;
}

// ---- baseline-PTX tensor + async ops ----
static __device__ __forceinline__ void ldsm_x4(uint32_t* r, uint32_t addr) {
    asm volatile("ldmatrix.sync.aligned.m8n8.x4.shared.b16 {%0,%1,%2,%3}, [%4];"
                 : "=r"(r[0]), "=r"(r[1]), "=r"(r[2]), "=r"(r[3]) : "r"(addr));
}
static __device__ __forceinline__ void ldsm_x2(uint32_t* r, uint32_t addr) {
    asm volatile("ldmatrix.sync.aligned.m8n8.x2.shared.b16 {%0,%1}, [%2];"
                 : "=r"(r[0]), "=r"(r[1]) : "r"(addr));
}
static __device__ __forceinline__ void mma_bf16(float* c, const uint32_t* a, const uint32_t* b) {
    asm volatile("mma.sync.aligned.m16n8k16.row.col.f32.bf16.bf16.f32 "
                 "{%0,%1,%2,%3}, {%4,%5,%6,%7}, {%8,%9}, {%0,%1,%2,%3};"
                 : "+f"(c[0]), "+f"(c[1]), "+f"(c[2]), "+f"(c[3])
                 : "r"(a[0]), "r"(a[1]), "r"(a[2]), "r"(a[3]), "r"(b[0]), "r"(b[1]));
}
static __device__ __forceinline__ void cp16(uint32_t smem, const void* gmem) {
    asm volatile("cp.async.cg.shared.global [%0], [%1], 16;" :: "r"(smem), "l"(gmem));
}
#define CP_COMMIT() asm volatile("cp.async.commit_group;" ::: "memory")
#define CP_WAIT(N)  asm volatile("cp.async.wait_group %0;" :: "n"(N) : "memory")

// ---- mask dtype detection: 0=u8, 1=i32, 2=f32, 3=bf16 ----
__global__ void k_detect(const unsigned int* __restrict__ m) {
    __shared__ int c[4];
    int t = threadIdx.x;
    if (t < 4) c[t] = 0;
    __syncthreads();
    int cb = 0, cf = 0, ci = 0, co = 0;
    for (int i = t; i < 65536; i += 256) {
        unsigned v = m[i];
        if (!v) continue;
        if (v == 0x3F803F80u || v == 0x00003F80u) cb++;
        else if (v == 0x3F800000u) cf++;
        else if (v == 1u) ci++;
        else co++;
    }
    atomicAdd(&c[0], cb); atomicAdd(&c[1], cf); atomicAdd(&c[2], ci); atomicAdd(&c[3], co);
    __syncthreads();
    if (t == 0) {
        int mode;
        if      (c[0] > 64) mode = 3;
        else if (c[3] > 64) mode = 0;
        else if (c[1] > 64) mode = 2;
        else                mode = 1;
        g_mode = mode;
    }
}
static __device__ __forceinline__ float mask_at(const void* m, int mode, int idx) {
    if (mode == 2) return ((const float*)m)[idx] != 0.0f ? 1.0f : 0.0f;
    if (mode == 0) return ((const unsigned char*)m)[idx] ? 1.0f : 0.0f;
    if (mode == 1) return ((const int*)m)[idx] ? 1.0f : 0.0f;
    return ((const unsigned short*)m)[idx] ? 1.0f : 0.0f;
}

// ---- W split precompute: build swizzled smem images once ----
__global__ __launch_bounds__(256) void k_wsplit(const float* __restrict__ Wfg,
                                                const float* __restrict__ Wgo,
                                                const float* __restrict__ Wout) {
    const int tile = blockIdx.x;          // 0..3 fg, 4 go, 5 out
    const int tid = threadIdx.x;
    unsigned char* base = g_wimg + (size_t)tile * 65536;
    #pragma unroll
    for (int p = 0; p < 16; p++) {
        int idx = tid + 256 * p;          // 0..4095 float4
        int j = idx >> 5;                 // B-tile row 0..127
        int c4 = idx & 31;
        const float* src;
        if (tile < 4) {
            int pr = j >> 1;
            int e = (j & 1) ? (256 + tile * 64 + pr) : (tile * 64 + pr);
            src = Wfg + (size_t)e * DD;
        } else if (tile == 4) {
            src = Wgo + (size_t)j * DD;
        } else {
            src = Wout + (size_t)j * DD;
        }
        float4 v = *(const float4*)(src + c4 * 4);
        __nv_bfloat16 h0 = __float2bfloat16(v.x), h1 = __float2bfloat16(v.y);
        __nv_bfloat16 h2 = __float2bfloat16(v.z), h3 = __float2bfloat16(v.w);
        __nv_bfloat16 l0 = __float2bfloat16(v.x - __bfloat162float(h0));
        __nv_bfloat16 l1 = __float2bfloat16(v.y - __bfloat162float(h1));
        __nv_bfloat16 l2 = __float2bfloat16(v.z - __bfloat162float(h2));
        __nv_bfloat16 l3 = __float2bfloat16(v.w - __bfloat162float(h3));
        int hh = c4 >> 4;
        int c16 = (c4 & 15) >> 1;
        int sub = (c4 & 1) * 8;
        uint32_t off = (j << 7) + (c16 << 4);
        off ^= (off >> 3) & 0x70;
        *(uint2*)(base + hh * 16384 + off + sub)         = make_uint2(pkbf(h0, h1), pkbf(h2, h3));
        *(uint2*)(base + 32768 + hh * 16384 + off + sub) = make_uint2(pkbf(l0, l1), pkbf(l2, l3));
    }
}

// ---- Stage 1: LN1 over d -> bf16 hi/lo split, warp per row ----
__global__ __launch_bounds__(256) void k_ln(const float* __restrict__ edges,
                                            const float* __restrict__ w,
                                            const float* __restrict__ b) {
    int warp = threadIdx.x >> 5, lane = threadIdx.x & 31;
    size_t r = (size_t)blockIdx.x * 8 + warp;
    float4 v = *(const float4*)&edges[r * DD + lane * 4];
    float4 w4 = *(const float4*)&w[lane * 4];
    float4 b4 = *(const float4*)&b[lane * 4];
    float s = v.x + v.y + v.z + v.w;
    float q = v.x * v.x + v.y * v.y + v.z * v.z + v.w * v.w;
    #pragma unroll
    for (int o = 16; o; o >>= 1) {
        s += __shfl_xor_sync(0xffffffffu, s, o);
        q += __shfl_xor_sync(0xffffffffu, q, o);
    }
    float mu = s * (1.0f / DD);
    float var = q * (1.0f / DD) - mu * mu;
    float rs = rsqrtf(var + 1e-5f);
    float n0 = (v.x - mu) * rs * w4.x + b4.x;
    float n1 = (v.y - mu) * rs * w4.y + b4.y;
    float n2 = (v.z - mu) * rs * w4.z + b4.z;
    float n3 = (v.w - mu) * rs * w4.w + b4.w;
    __nv_bfloat16 h0 = __float2bfloat16(n0), h1 = __float2bfloat16(n1);
    __nv_bfloat16 h2 = __float2bfloat16(n2), h3 = __float2bfloat16(n3);
    __nv_bfloat16 l0 = __float2bfloat16(n0 - __bfloat162float(h0));
    __nv_bfloat16 l1 = __float2bfloat16(n1 - __bfloat162float(h1));
    __nv_bfloat16 l2 = __float2bfloat16(n2 - __bfloat162float(h2));
    __nv_bfloat16 l3 = __float2bfloat16(n3 - __bfloat162float(h3));
    *(uint2*)&g_xhi[r * DD + lane * 4] = make_uint2(pkbf(h0, h1), pkbf(h2, h3));
    *(uint2*)&g_xlo[r * DD + lane * 4] = make_uint2(pkbf(l0, l1), pkbf(l2, l3));
}

// ---- Stage 2: fused projection via HMMA; x tile loaded once, 5 W tiles looped ----
// smem: x hi [0,32KB) halves, x lo [32KB,64KB), W double buffer at 64KB and 128KB.
#define FG_SMEM (65536 + 2*65536)
__global__ __launch_bounds__(256) void k_fg(const void*  __restrict__ mask,
                                            const float* __restrict__ bfg,
                                            const float* __restrict__ bgo) {
    extern __shared__ char smc[];
    const uint32_t sb = smem_u32(smc);
    const int tid = threadIdx.x;
    const int wid = tid >> 5, lane = tid & 31;
    const int row0 = blockIdx.x * 128;
    const int mode = g_mode;
    const int wm = wid >> 1, wn = wid & 1;

    // x hi/lo -> swizzled smem via cp.async
    #pragma unroll
    for (int p = 0; p < 16; p++) {
        int idx = tid + 256 * p;            // 0..4095 chunks
        int s = idx >> 11;
        int rem = idx & 2047;
        int row = rem >> 4;
        int u = rem & 15;
        int h = u >> 3, c16 = u & 7;
        const __nv_bfloat16* src = (s ? g_xlo : g_xhi) + (size_t)(row0 + row) * DD + h * 64 + c16 * 8;
        uint32_t off = (row << 7) + (c16 << 4);
        off ^= (off >> 3) & 0x70;
        cp16(sb + s * 32768 + h * 16384 + off, src);
    }
    // W tile 0 into buffer 0
    #pragma unroll
    for (int p = 0; p < 16; p++) {
        int idx = tid + 256 * p;
        cp16(sb + 65536 + idx * 16, g_wimg + idx * 16);
    }
    CP_COMMIT();                            // G0 = x + W0
    #pragma unroll
    for (int p = 0; p < 16; p++) {
        int idx = tid + 256 * p;
        cp16(sb + 131072 + idx * 16, g_wimg + 65536 + idx * 16);
    }
    CP_COMMIT();                            // G1 = W1

    #pragma unroll 1
    for (int nt = 0; nt < 5; nt++) {
        if (nt < 4) { CP_WAIT(1); } else { CP_WAIT(0); }
        __syncthreads();
        const uint32_t wb = sb + 65536 + (uint32_t)(nt & 1) * 65536;

        float acc[2][8][4];
        #pragma unroll
        for (int mt = 0; mt < 2; mt++)
            #pragma unroll
            for (int nf = 0; nf < 8; nf++)
                #pragma unroll
                for (int q = 0; q < 4; q++) acc[mt][nf][q] = 0.0f;

        #pragma unroll
        for (int ks = 0; ks < 8; ks++) {
            int h = ks >> 2, kk = ks & 3;
            uint32_t b_hi[8][2], b_lo[8][2];
            #pragma unroll
            for (int nf = 0; nf < 8; nf++) {
                uint32_t off = ((uint32_t)(wn * 64 + nf * 8 + (lane & 7)) << 7)
                             + ((uint32_t)kk << 5) + (((uint32_t)(lane >> 3) & 1) << 4);
                off ^= (off >> 3) & 0x70;
                ldsm_x2(b_hi[nf], wb + h * 16384 + off);
                ldsm_x2(b_lo[nf], wb + 32768 + h * 16384 + off);
            }
            #pragma unroll
            for (int mt = 0; mt < 2; mt++) {
                uint32_t a_hi[4], a_lo[4];
                uint32_t off = ((uint32_t)(wm * 32 + mt * 16 + (lane & 15)) << 7)
                             + ((uint32_t)kk << 5) + ((uint32_t)(lane >> 4) << 4);
                off ^= (off >> 3) & 0x70;
                ldsm_x4(a_hi, sb + h * 16384 + off);
                ldsm_x4(a_lo, sb + 32768 + h * 16384 + off);
                #pragma unroll
                for (int nf = 0; nf < 8; nf++) {
                    mma_bf16(acc[mt][nf], a_hi, b_hi[nf]);
                    mma_bf16(acc[mt][nf], a_hi, b_lo[nf]);
                    mma_bf16(acc[mt][nf], a_lo, b_hi[nf]);
                }
            }
        }

        if (nt < 4) {
            #pragma unroll
            for (int nf = 0; nf < 8; nf++) {
                int f = nt * 64 + wn * 32 + nf * 4 + (lane & 3);
                float bf = bfg[f], bg = bfg[256 + f];
                __nv_bfloat16* ph; __nv_bfloat16* pl;
                if (f < 128) { ph = g_to_hi + (size_t)f * NROWS;         pl = g_to_lo + (size_t)f * NROWS; }
                else         { ph = g_fr_hi + (size_t)(f - 128) * NROWS; pl = g_fr_lo + (size_t)(f - 128) * NROWS; }
                #pragma unroll
                for (int mt = 0; mt < 2; mt++) {
                    int r = row0 + wm * 32 + mt * 16 + (lane >> 2);
                    float mv0 = mask_at(mask, mode, r);
                    float mv1 = mask_at(mask, mode, r + 8);
                    float v0 = (acc[mt][nf][0] + bf) * sigm(acc[mt][nf][1] + bg) * mv0;
                    float v1 = (acc[mt][nf][2] + bf) * sigm(acc[mt][nf][3] + bg) * mv1;
                    __nv_bfloat16 h0 = __float2bfloat16(v0);
                    __nv_bfloat16 l0 = __float2bfloat16(v0 - __bfloat162float(h0));
                    __nv_bfloat16 h1 = __float2bfloat16(v1);
                    __nv_bfloat16 l1 = __float2bfloat16(v1 - __bfloat162float(h1));
                    ph[r] = h0;     pl[r] = l0;
                    ph[r + 8] = h1; pl[r + 8] = l1;
                }
            }
        } else {
            #pragma unroll
            for (int nf = 0; nf < 8; nf++) {
                int e = wn * 64 + nf * 8 + (lane & 3) * 2;
                float b0 = bgo[e], b1 = bgo[e + 1];
                #pragma unroll
                for (int mt = 0; mt < 2; mt++) {
                    int r = row0 + wm * 32 + mt * 16 + (lane >> 2);
                    float mv0 = mask_at(mask, mode, r);
                    float mv1 = mask_at(mask, mode, r + 8);
                    *(float2*)&g_og[(size_t)r * DD + e] =
                        make_float2(sigm(acc[mt][nf][0] + b0) * mv0, sigm(acc[mt][nf][1] + b1) * mv0);
                    *(float2*)&g_og[(size_t)(r + 8) * DD + e] =
                        make_float2(sigm(acc[mt][nf][2] + b0) * mv1, sigm(acc[mt][nf][3] + b1) * mv1);
                }
            }
        }
        __syncthreads();
        if (nt + 2 <= 4) {
            const unsigned char* src = g_wimg + (size_t)(nt + 2) * 65536;
            uint32_t dst = sb + 65536 + (uint32_t)(nt & 1) * 65536;
            #pragma unroll
            for (int p = 0; p < 16; p++) {
                int idx = tid + 256 * p;
                cp16(dst + idx * 16, src + idx * 16);
            }
            CP_COMMIT();
        }
    }
}

// ---- Stage 3: tri via HMMA + cp.async double buffering ----
#define TRI_SMEM 65536
static __device__ __forceinline__ uint32_t sw64(uint32_t row, uint32_t chunk) {
    return (row << 6) + (((chunk ^ (row >> 1)) & 3) << 4);
}
__global__ __launch_bounds__(256, 2) void k_tri() {
    extern __shared__ char smc[];
    const uint32_t sb = smem_u32(smc);
    const int tid = threadIdx.x;
    const int wid = tid >> 5, lane = tid & 31;
    const int j0 = blockIdx.x * 128, i0 = blockIdx.y * 128, d = blockIdx.z;
    const int wm = wid >> 2, wn = wid & 3;

    float acc[4][4][4];
    #pragma unroll
    for (int mt = 0; mt < 4; mt++)
        #pragma unroll
        for (int nt = 0; nt < 4; nt++)
            #pragma unroll
            for (int q = 0; q < 4; q++) acc[mt][nt][q] = 0.0f;

    const __nv_bfloat16* srcs[4] = {
        g_to_hi + (size_t)d * NROWS + (size_t)i0 * NN,
        g_to_lo + (size_t)d * NROWS + (size_t)i0 * NN,
        g_fr_hi + (size_t)d * NROWS + (size_t)j0 * NN,
        g_fr_lo + (size_t)d * NROWS + (size_t)j0 * NN
    };

    auto load_slab = [&](int kp, int buf) {
        uint32_t bb = sb + buf * 32768;
        #pragma unroll
        for (int p = 0; p < 8; p++) {
            int idx = tid + 256 * p;
            int t = idx >> 9;
            int r = (idx >> 2) & 127;
            int c = idx & 3;
            cp16(bb + t * 8192 + sw64(r, c), srcs[t] + (size_t)r * NN + kp * 32 + c * 8);
        }
        CP_COMMIT();
    };

    load_slab(0, 0);
    for (int kp = 0; kp < 16; kp++) {
        if (kp < 15) {
            load_slab(kp + 1, (kp + 1) & 1);
            CP_WAIT(1);
        } else {
            CP_WAIT(0);
        }
        __syncthreads();

        uint32_t bb = sb + (kp & 1) * 32768;
        #pragma unroll
        for (int ks = 0; ks < 2; ks++) {
            uint32_t b_hi[4][2], b_lo[4][2];
            #pragma unroll
            for (int nt = 0; nt < 4; nt++) {
                uint32_t off = sw64((uint32_t)(wn * 32 + nt * 8 + (lane & 7)),
                                    (uint32_t)(ks * 2 + ((lane >> 3) & 1)));
                ldsm_x2(b_hi[nt], bb + 16384 + off);
                ldsm_x2(b_lo[nt], bb + 24576 + off);
            }
            #pragma unroll
            for (int mt = 0; mt < 4; mt++) {
                uint32_t a_hi[4], a_lo[4];
                uint32_t off = sw64((uint32_t)(wm * 64 + mt * 16 + (lane & 15)),
                                    (uint32_t)(ks * 2 + (lane >> 4)));
                ldsm_x4(a_hi, bb + off);
                ldsm_x4(a_lo, bb + 8192 + off);
                #pragma unroll
                for (int nt = 0; nt < 4; nt++) {
                    mma_bf16(acc[mt][nt], a_hi, b_hi[nt]);
                    mma_bf16(acc[mt][nt], a_hi, b_lo[nt]);
                    mma_bf16(acc[mt][nt], a_lo, b_hi[nt]);
                }
            }
        }
        __syncthreads();
    }

    #pragma unroll
    for (int mt = 0; mt < 4; mt++) {
        int i = i0 + wm * 64 + mt * 16 + (lane >> 2);
        #pragma unroll
        for (int nt = 0; nt < 4; nt++) {
            int j = j0 + wn * 32 + nt * 8 + (lane & 3) * 2;
            size_t base = (size_t)d * NROWS + (size_t)i * NN + j;
            *(float2*)&g_x[base]          = make_float2(acc[mt][nt][0], acc[mt][nt][1]);
            *(float2*)&g_x[base + 8 * NN] = make_float2(acc[mt][nt][2], acc[mt][nt][3]);
        }
    }
}

// ---- Stage 4: LN2(tri planar) -> bf16 split -> HMMA with W_out, times out_gate ----
// smem: A hi [0,32KB), A lo [32KB,64KB), W image [64KB,128KB), ys[128][133] at 128KB.
#define OUT_SMEM (131072 + 128*133*4)
__global__ __launch_bounds__(256) void k_out(const float* __restrict__ ln2w,
                                             const float* __restrict__ ln2b,
                                             const float* __restrict__ bout,
                                             float* __restrict__ out) {
    extern __shared__ char smc[];
    const uint32_t sb = smem_u32(smc);
    float* ys = (float*)(smc + 131072);
    const int tid = threadIdx.x;
    const int wid = tid >> 5, lane = tid & 31;
    const int row0 = blockIdx.x * 128;
    const int wm = wid >> 1, wn = wid & 1;

    // W_out image via cp.async (overlaps gather + LN below)
    #pragma unroll
    for (int p = 0; p < 16; p++) {
        int idx = tid + 256 * p;
        cp16(sb + 65536 + idx * 16, g_wimg + 5 * 65536 + idx * 16);
    }
    CP_COMMIT();

    // planar tri gather -> fp32 staging
    #pragma unroll 8
    for (int p = 0; p < 64; p++) {
        int idx = tid + 256 * p;
        int row = idx & 127, dd = idx >> 7;
        ys[row * 133 + dd] = g_x[(size_t)dd * NROWS + row0 + row];
    }
    __syncthreads();

    // LN2 per row -> bf16 hi/lo into A region
    {
        float w4[4], b4[4];
        #pragma unroll
        for (int q = 0; q < 4; q++) { w4[q] = ln2w[lane * 4 + q]; b4[q] = ln2b[lane * 4 + q]; }
        int dd = lane * 4;
        int hh = dd >> 6;
        uint32_t offb = (uint32_t)((dd & 63) * 2);
        #pragma unroll
        for (int rr = 0; rr < 16; rr++) {
            int row = wid * 16 + rr;
            float* yr = &ys[row * 133 + dd];
            float v0 = yr[0], v1 = yr[1], v2 = yr[2], v3 = yr[3];
            float s = v0 + v1 + v2 + v3;
            float q2 = v0 * v0 + v1 * v1 + v2 * v2 + v3 * v3;
            #pragma unroll
            for (int o = 16; o; o >>= 1) {
                s  += __shfl_xor_sync(0xffffffffu, s, o);
                q2 += __shfl_xor_sync(0xffffffffu, q2, o);
            }
            float mu = s * (1.0f / DD);
            float var = q2 * (1.0f / DD) - mu * mu;
            float rs = rsqrtf(var + 1e-5f);
            float n0 = (v0 - mu) * rs * w4[0] + b4[0];
            float n1 = (v1 - mu) * rs * w4[1] + b4[1];
            float n2 = (v2 - mu) * rs * w4[2] + b4[2];
            float n3 = (v3 - mu) * rs * w4[3] + b4[3];
            __nv_bfloat16 h0 = __float2bfloat16(n0), h1 = __float2bfloat16(n1);
            __nv_bfloat16 h2 = __float2bfloat16(n2), h3 = __float2bfloat16(n3);
            __nv_bfloat16 l0 = __float2bfloat16(n0 - __bfloat162float(h0));
            __nv_bfloat16 l1 = __float2bfloat16(n1 - __bfloat162float(h1));
            __nv_bfloat16 l2 = __float2bfloat16(n2 - __bfloat162float(h2));
            __nv_bfloat16 l3 = __float2bfloat16(n3 - __bfloat162float(h3));
            uint32_t off = ((uint32_t)row << 7) + offb;
            off ^= (off >> 3) & 0x70;
            *(uint2*)(smc + hh * 16384 + off)         = make_uint2(pkbf(h0, h1), pkbf(h2, h3));
            *(uint2*)(smc + 32768 + hh * 16384 + off) = make_uint2(pkbf(l0, l1), pkbf(l2, l3));
        }
    }
    CP_WAIT(0);
    __syncthreads();

    float acc[2][8][4];
    #pragma unroll
    for (int mt = 0; mt < 2; mt++)
        #pragma unroll
        for (int nf = 0; nf < 8; nf++)
            #pragma unroll
            for (int q = 0; q < 4; q++) acc[mt][nf][q] = 0.0f;

    #pragma unroll
    for (int ks = 0; ks < 8; ks++) {
        int h = ks >> 2, kk = ks & 3;
        uint32_t b_hi[8][2], b_lo[8][2];
        #pragma unroll
        for (int nf = 0; nf < 8; nf++) {
            uint32_t off = ((uint32_t)(wn * 64 + nf * 8 + (lane & 7)) << 7)
                         + ((uint32_t)kk << 5) + (((uint32_t)(lane >> 3) & 1) << 4);
            off ^= (off >> 3) & 0x70;
            ldsm_x2(b_hi[nf], sb + 65536 + h * 16384 + off);
            ldsm_x2(b_lo[nf], sb + 98304 + h * 16384 + off);
        }
        #pragma unroll
        for (int mt = 0; mt < 2; mt++) {
            uint32_t a_hi[4], a_lo[4];
            uint32_t off = ((uint32_t)(wm * 32 + mt * 16 + (lane & 15)) << 7)
                         + ((uint32_t)kk << 5) + ((uint32_t)(lane >> 4) << 4);
            off ^= (off >> 3) & 0x70;
            ldsm_x4(a_hi, sb + h * 16384 + off);
            ldsm_x4(a_lo, sb + 32768 + h * 16384 + off);
            #pragma unroll
            for (int nf = 0; nf < 8; nf++) {
                mma_bf16(acc[mt][nf], a_hi, b_hi[nf]);
                mma_bf16(acc[mt][nf], a_hi, b_lo[nf]);
                mma_bf16(acc[mt][nf], a_lo, b_hi[nf]);
            }
        }
    }

    #pragma unroll
    for (int nf = 0; nf < 8; nf++) {
        int col = wn * 64 + nf * 8 + (lane & 3) * 2;
        float b0 = bout[col], b1 = bout[col + 1];
        #pragma unroll
        for (int mt = 0; mt < 2; mt++) {
            int r = row0 + wm * 32 + mt * 16 + (lane >> 2);
            size_t base = (size_t)r * DD + col;
            float2 og0 = *(const float2*)&g_og[base];
            *(float2*)&out[base] = make_float2(og0.x * (acc[mt][nf][0] + b0),
                                               og0.y * (acc[mt][nf][1] + b1));
            float2 og1 = *(const float2*)&g_og[base + 8 * DD];
            *(float2*)&out[base + 8 * DD] = make_float2(og1.x * (acc[mt][nf][2] + b0),
                                                        og1.y * (acc[mt][nf][3] + b1));
        }
    }
}

extern "C" void kernel_launch(void* const* d_in, const int* in_sizes, int n_in,
                              void* d_out, int out_size) {
    const float* edges = (const float*)d_in[0];
    const void*  mask  = d_in[1];
    const float* ln1w  = (const float*)d_in[2];
    const float* ln1b  = (const float*)d_in[3];
    const float* Wfg   = (const float*)d_in[4];
    const float* bfg   = (const float*)d_in[5];
    const float* Wgo   = (const float*)d_in[6];
    const float* bgo   = (const float*)d_in[7];
    const float* ln2w  = (const float*)d_in[8];
    const float* ln2b  = (const float*)d_in[9];
    const float* Wout  = (const float*)d_in[10];
    const float* bout  = (const float*)d_in[11];
    float* out = (float*)d_out;

    cudaFuncSetAttribute(k_fg,  cudaFuncAttributeMaxDynamicSharedMemorySize, FG_SMEM);
    cudaFuncSetAttribute(k_tri, cudaFuncAttributeMaxDynamicSharedMemorySize, TRI_SMEM);
    cudaFuncSetAttribute(k_out, cudaFuncAttributeMaxDynamicSharedMemorySize, OUT_SMEM);

    k_detect<<<1, 256>>>((const unsigned int*)mask);
    k_wsplit<<<6, 256>>>(Wfg, Wgo, Wout);
    k_ln<<<NROWS / 8, 256>>>(edges, ln1w, ln1b);
    k_fg<<<NROWS / 128, 256, FG_SMEM>>>(mask, bfg, bgo);
    k_tri<<<dim3(NN / 128, NN / 128, DD), 256, TRI_SMEM>>>();
    k_out<<<NROWS / 128, 256, OUT_SMEM>>>(ln2w, ln2b, bout, out);
}

// round 16
// speedup vs baseline: 2.6694x; 1.1100x over previous
#include <cuda_runtime.h>
#include <cuda_bf16.h>
#include <math.h>
#include <stdint.h>

#define NN 512
#define DD 128
#define NROWS (NN*NN)
typedef unsigned long long ull;

// ---- scratch (device globals; allocation is forbidden) ----
__device__ float g_x[NROWS*DD];                 // tri planar [d][i*NN+j]
__device__ float g_og[NROWS*DD];                // out_gate [row][d]
__device__ __nv_bfloat16 g_xhi[(size_t)NROWS*DD];
__device__ __nv_bfloat16 g_xlo[(size_t)NROWS*DD];
__device__ __nv_bfloat16 g_to_hi[(size_t)DD*NROWS];
__device__ __nv_bfloat16 g_to_lo[(size_t)DD*NROWS];
__device__ __nv_bfloat16 g_fr_hi[(size_t)DD*NROWS];
__device__ __nv_bfloat16 g_fr_lo[(size_t)DD*NROWS];
// Pre-split, pre-swizzled W smem images: tiles 0..3 = fg pairs, 4 = go, 5 = Wout.
__device__ __align__(16) unsigned char g_wimg[6*65536];
__device__ int g_mode;

static __device__ __forceinline__ float sigm(float x) { return 1.0f / (1.0f + __expf(-x)); }

static __device__ __forceinline__ uint32_t smem_u32(const void* p) {
    uint32_t a;
    asm("{ .reg .u64 t; cvta.to.shared.u64 t, %1; cvt.u32.u64 %0, t; }" : "=r"(a) : "l"(p));
    return a;
}
static __device__ __forceinline__ uint32_t pkbf(__nv_bfloat16 a, __nv_bfloat16 b) {
    __nv_bfloat162 t; t.x = a; t.y = b;
    return *(uint32_t*)&t;
}

// ---- baseline-PTX tensor + async ops ----
static __device__ __forceinline__ void ldsm_x4(uint32_t* r, uint32_t addr) {
    asm volatile("ldmatrix.sync.aligned.m8n8.x4.shared.b16 {%0,%1,%2,%3}, [%4];"
                 : "=r"(r[0]), "=r"(r[1]), "=r"(r[2]), "=r"(r[3]) : "r"(addr));
}
static __device__ __forceinline__ void mma_bf16r(float* c, const uint32_t* a, uint32_t b0, uint32_t b1) {
    asm volatile("mma.sync.aligned.m16n8k16.row.col.f32.bf16.bf16.f32 "
                 "{%0,%1,%2,%3}, {%4,%5,%6,%7}, {%8,%9}, {%0,%1,%2,%3};"
                 : "+f"(c[0]), "+f"(c[1]), "+f"(c[2]), "+f"(c[3])
                 : "r"(a[0]), "r"(a[1]), "r"(a[2]), "r"(a[3]), "r"(b0), "r"(b1));
}
static __device__ __forceinline__ void cp16(uint32_t smem, const void* gmem) {
    asm volatile("cp.async.cg.shared.global [%0], [%1], 16;" :: "r"(smem), "l"(gmem));
}
#define CP_COMMIT() asm volatile("cp.async.commit_group;" ::: "memory")
#define CP_WAIT(N)  asm volatile("cp.async.wait_group %0;" :: "n"(N) : "memory")

// ---- mask dtype detection: 0=u8, 1=i32, 2=f32, 3=bf16 ----
__global__ void k_detect(const unsigned int* __restrict__ m) {
    __shared__ int c[4];
    int t = threadIdx.x;
    if (t < 4) c[t] = 0;
    __syncthreads();
    int cb = 0, cf = 0, ci = 0, co = 0;
    for (int i = t; i < 65536; i += 256) {
        unsigned v = m[i];
        if (!v) continue;
        if (v == 0x3F803F80u || v == 0x00003F80u) cb++;
        else if (v == 0x3F800000u) cf++;
        else if (v == 1u) ci++;
        else co++;
    }
    atomicAdd(&c[0], cb); atomicAdd(&c[1], cf); atomicAdd(&c[2], ci); atomicAdd(&c[3], co);
    __syncthreads();
    if (t == 0) {
        int mode;
        if      (c[0] > 64) mode = 3;
        else if (c[3] > 64) mode = 0;
        else if (c[1] > 64) mode = 2;
        else                mode = 1;
        g_mode = mode;
    }
}
static __device__ __forceinline__ float mask_at(const void* m, int mode, int idx) {
    if (mode == 2) return ((const float*)m)[idx] != 0.0f ? 1.0f : 0.0f;
    if (mode == 0) return ((const unsigned char*)m)[idx] ? 1.0f : 0.0f;
    if (mode == 1) return ((const int*)m)[idx] ? 1.0f : 0.0f;
    return ((const unsigned short*)m)[idx] ? 1.0f : 0.0f;
}

// ---- W split precompute ----
__global__ __launch_bounds__(256) void k_wsplit(const float* __restrict__ Wfg,
                                                const float* __restrict__ Wgo,
                                                const float* __restrict__ Wout) {
    const int tile = blockIdx.x;
    const int tid = threadIdx.x;
    unsigned char* base = g_wimg + (size_t)tile * 65536;
    #pragma unroll
    for (int p = 0; p < 16; p++) {
        int idx = tid + 256 * p;
        int j = idx >> 5;
        int c4 = idx & 31;
        const float* src;
        if (tile < 4) {
            int pr = j >> 1;
            int e = (j & 1) ? (256 + tile * 64 + pr) : (tile * 64 + pr);
            src = Wfg + (size_t)e * DD;
        } else if (tile == 4) {
            src = Wgo + (size_t)j * DD;
        } else {
            src = Wout + (size_t)j * DD;
        }
        float4 v = *(const float4*)(src + c4 * 4);
        __nv_bfloat16 h0 = __float2bfloat16(v.x), h1 = __float2bfloat16(v.y);
        __nv_bfloat16 h2 = __float2bfloat16(v.z), h3 = __float2bfloat16(v.w);
        __nv_bfloat16 l0 = __float2bfloat16(v.x - __bfloat162float(h0));
        __nv_bfloat16 l1 = __float2bfloat16(v.y - __bfloat162float(h1));
        __nv_bfloat16 l2 = __float2bfloat16(v.z - __bfloat162float(h2));
        __nv_bfloat16 l3 = __float2bfloat16(v.w - __bfloat162float(h3));
        int hh = c4 >> 4;
        int c16 = (c4 & 15) >> 1;
        int sub = (c4 & 1) * 8;
        uint32_t off = (j << 7) + (c16 << 4);
        off ^= (off >> 3) & 0x70;
        *(uint2*)(base + hh * 16384 + off + sub)         = make_uint2(pkbf(h0, h1), pkbf(h2, h3));
        *(uint2*)(base + 32768 + hh * 16384 + off + sub) = make_uint2(pkbf(l0, l1), pkbf(l2, l3));
    }
}

// ---- Stage 1: LN1 -> bf16 hi/lo, warp per row ----
__global__ __launch_bounds__(256) void k_ln(const float* __restrict__ edges,
                                            const float* __restrict__ w,
                                            const float* __restrict__ b) {
    int warp = threadIdx.x >> 5, lane = threadIdx.x & 31;
    size_t r = (size_t)blockIdx.x * 8 + warp;
    float4 v = *(const float4*)&edges[r * DD + lane * 4];
    float4 w4 = *(const float4*)&w[lane * 4];
    float4 b4 = *(const float4*)&b[lane * 4];
    float s = v.x + v.y + v.z + v.w;
    float q = v.x * v.x + v.y * v.y + v.z * v.z + v.w * v.w;
    #pragma unroll
    for (int o = 16; o; o >>= 1) {
        s += __shfl_xor_sync(0xffffffffu, s, o);
        q += __shfl_xor_sync(0xffffffffu, q, o);
    }
    float mu = s * (1.0f / DD);
    float var = q * (1.0f / DD) - mu * mu;
    float rs = rsqrtf(var + 1e-5f);
    float n0 = (v.x - mu) * rs * w4.x + b4.x;
    float n1 = (v.y - mu) * rs * w4.y + b4.y;
    float n2 = (v.z - mu) * rs * w4.z + b4.z;
    float n3 = (v.w - mu) * rs * w4.w + b4.w;
    __nv_bfloat16 h0 = __float2bfloat16(n0), h1 = __float2bfloat16(n1);
    __nv_bfloat16 h2 = __float2bfloat16(n2), h3 = __float2bfloat16(n3);
    __nv_bfloat16 l0 = __float2bfloat16(n0 - __bfloat162float(h0));
    __nv_bfloat16 l1 = __float2bfloat16(n1 - __bfloat162float(h1));
    __nv_bfloat16 l2 = __float2bfloat16(n2 - __bfloat162float(h2));
    __nv_bfloat16 l3 = __float2bfloat16(n3 - __bfloat162float(h3));
    *(uint2*)&g_xhi[r * DD + lane * 4] = make_uint2(pkbf(h0, h1), pkbf(h2, h3));
    *(uint2*)&g_xlo[r * DD + lane * 4] = make_uint2(pkbf(l0, l1), pkbf(l2, l3));
}

// ---- Stage 2: fused projection, 512 threads / 16 warps ----
// smem: x hi [0,32KB), x lo [32KB,64KB), W double buffer at 64KB / 128KB.
#define FG_SMEM (65536 + 2*65536)
__global__ __launch_bounds__(512) void k_fg(const void*  __restrict__ mask,
                                            const float* __restrict__ bfg,
                                            const float* __restrict__ bgo) {
    extern __shared__ char smc[];
    const uint32_t sb = smem_u32(smc);
    const int tid = threadIdx.x;
    const int wid = tid >> 5, lane = tid & 31;
    const int row0 = blockIdx.x * 128;
    const int mode = g_mode;
    const int wm = wid >> 1, wn = wid & 1;   // 8 m-warps x 2 n-warps

    // x hi/lo -> swizzled smem
    #pragma unroll
    for (int p = 0; p < 8; p++) {
        int idx = tid + 512 * p;            // 0..4095 chunks
        int s = idx >> 11;
        int rem = idx & 2047;
        int row = rem >> 4;
        int u = rem & 15;
        int h = u >> 3, c16 = u & 7;
        const __nv_bfloat16* src = (s ? g_xlo : g_xhi) + (size_t)(row0 + row) * DD + h * 64 + c16 * 8;
        uint32_t off = (row << 7) + (c16 << 4);
        off ^= (off >> 3) & 0x70;
        cp16(sb + s * 32768 + h * 16384 + off, src);
    }
    #pragma unroll
    for (int p = 0; p < 8; p++) {
        int idx = tid + 512 * p;
        cp16(sb + 65536 + idx * 16, g_wimg + idx * 16);
    }
    CP_COMMIT();
    #pragma unroll
    for (int p = 0; p < 8; p++) {
        int idx = tid + 512 * p;
        cp16(sb + 131072 + idx * 16, g_wimg + 65536 + idx * 16);
    }
    CP_COMMIT();

    #pragma unroll 1
    for (int nt = 0; nt < 5; nt++) {
        if (nt < 4) { CP_WAIT(1); } else { CP_WAIT(0); }
        __syncthreads();
        const uint32_t wb = sb + 65536 + (uint32_t)(nt & 1) * 65536;

        float acc[8][4];
        #pragma unroll
        for (int nf = 0; nf < 8; nf++)
            #pragma unroll
            for (int q = 0; q < 4; q++) acc[nf][q] = 0.0f;

        #pragma unroll
        for (int ks = 0; ks < 8; ks++) {
            int h = ks >> 2, kk = ks & 3;
            // B pairs via ldsm_x4: rows wn*64 + nfp*16 + pairbit*8 + (lane&7)
            uint32_t b_hi[4][4], b_lo[4][4];
            #pragma unroll
            for (int nfp = 0; nfp < 4; nfp++) {
                uint32_t row = (uint32_t)(wn * 64 + nfp * 16 + ((lane >> 3) & 1) * 8 + (lane & 7));
                uint32_t off = (row << 7) + ((uint32_t)kk << 5) + ((uint32_t)(lane >> 4) << 4);
                off ^= (off >> 3) & 0x70;
                ldsm_x4(b_hi[nfp], wb + h * 16384 + off);
                ldsm_x4(b_lo[nfp], wb + 32768 + h * 16384 + off);
            }
            uint32_t a_hi[4], a_lo[4];
            {
                uint32_t row = (uint32_t)(wm * 16 + (lane & 15));
                uint32_t off = (row << 7) + ((uint32_t)kk << 5) + ((uint32_t)(lane >> 4) << 4);
                off ^= (off >> 3) & 0x70;
                ldsm_x4(a_hi, sb + h * 16384 + off);
                ldsm_x4(a_lo, sb + 32768 + h * 16384 + off);
            }
            #pragma unroll
            for (int nfp = 0; nfp < 4; nfp++) {
                // even nf: {r0,r2}; odd nf: {r1,r3}
                mma_bf16r(acc[2*nfp],   a_hi, b_hi[nfp][0], b_hi[nfp][2]);
                mma_bf16r(acc[2*nfp],   a_hi, b_lo[nfp][0], b_lo[nfp][2]);
                mma_bf16r(acc[2*nfp],   a_lo, b_hi[nfp][0], b_hi[nfp][2]);
                mma_bf16r(acc[2*nfp+1], a_hi, b_hi[nfp][1], b_hi[nfp][3]);
                mma_bf16r(acc[2*nfp+1], a_hi, b_lo[nfp][1], b_lo[nfp][3]);
                mma_bf16r(acc[2*nfp+1], a_lo, b_hi[nfp][1], b_hi[nfp][3]);
            }
        }

        int r = row0 + wm * 16 + (lane >> 2);
        float mv0 = mask_at(mask, mode, r);
        float mv1 = mask_at(mask, mode, r + 8);
        if (nt < 4) {
            #pragma unroll
            for (int nf = 0; nf < 8; nf++) {
                int f = nt * 64 + wn * 32 + nf * 4 + (lane & 3);
                float bf = bfg[f], bg = bfg[256 + f];
                __nv_bfloat16* ph; __nv_bfloat16* pl;
                if (f < 128) { ph = g_to_hi + (size_t)f * NROWS;         pl = g_to_lo + (size_t)f * NROWS; }
                else         { ph = g_fr_hi + (size_t)(f - 128) * NROWS; pl = g_fr_lo + (size_t)(f - 128) * NROWS; }
                float v0 = (acc[nf][0] + bf) * sigm(acc[nf][1] + bg) * mv0;
                float v1 = (acc[nf][2] + bf) * sigm(acc[nf][3] + bg) * mv1;
                __nv_bfloat16 h0 = __float2bfloat16(v0);
                __nv_bfloat16 l0 = __float2bfloat16(v0 - __bfloat162float(h0));
                __nv_bfloat16 h1 = __float2bfloat16(v1);
                __nv_bfloat16 l1 = __float2bfloat16(v1 - __bfloat162float(h1));
                ph[r] = h0;     pl[r] = l0;
                ph[r + 8] = h1; pl[r + 8] = l1;
            }
        } else {
            #pragma unroll
            for (int nf = 0; nf < 8; nf++) {
                int e = wn * 64 + nf * 8 + (lane & 3) * 2;
                float b0 = bgo[e], b1 = bgo[e + 1];
                *(float2*)&g_og[(size_t)r * DD + e] =
                    make_float2(sigm(acc[nf][0] + b0) * mv0, sigm(acc[nf][1] + b1) * mv0);
                *(float2*)&g_og[(size_t)(r + 8) * DD + e] =
                    make_float2(sigm(acc[nf][2] + b0) * mv1, sigm(acc[nf][3] + b1) * mv1);
            }
        }
        __syncthreads();
        if (nt + 2 <= 4) {
            const unsigned char* src = g_wimg + (size_t)(nt + 2) * 65536;
            uint32_t dst = sb + 65536 + (uint32_t)(nt & 1) * 65536;
            #pragma unroll
            for (int p = 0; p < 8; p++) {
                int idx = tid + 512 * p;
                cp16(dst + idx * 16, src + idx * 16);
            }
            CP_COMMIT();
        }
    }
}

// ---- Stage 3: tri via HMMA + cp.async double buffering (B x4 pairing) ----
#define TRI_SMEM 65536
static __device__ __forceinline__ uint32_t sw64(uint32_t row, uint32_t chunk) {
    return (row << 6) + (((chunk ^ (row >> 1)) & 3) << 4);
}
__global__ __launch_bounds__(256, 2) void k_tri() {
    extern __shared__ char smc[];
    const uint32_t sb = smem_u32(smc);
    const int tid = threadIdx.x;
    const int wid = tid >> 5, lane = tid & 31;
    const int j0 = blockIdx.x * 128, i0 = blockIdx.y * 128, d = blockIdx.z;
    const int wm = wid >> 2, wn = wid & 3;

    float acc[4][4][4];
    #pragma unroll
    for (int mt = 0; mt < 4; mt++)
        #pragma unroll
        for (int nt = 0; nt < 4; nt++)
            #pragma unroll
            for (int q = 0; q < 4; q++) acc[mt][nt][q] = 0.0f;

    const __nv_bfloat16* srcs[4] = {
        g_to_hi + (size_t)d * NROWS + (size_t)i0 * NN,
        g_to_lo + (size_t)d * NROWS + (size_t)i0 * NN,
        g_fr_hi + (size_t)d * NROWS + (size_t)j0 * NN,
        g_fr_lo + (size_t)d * NROWS + (size_t)j0 * NN
    };

    auto load_slab = [&](int kp, int buf) {
        uint32_t bb = sb + buf * 32768;
        #pragma unroll
        for (int p = 0; p < 8; p++) {
            int idx = tid + 256 * p;
            int t = idx >> 9;
            int r = (idx >> 2) & 127;
            int c = idx & 3;
            cp16(bb + t * 8192 + sw64(r, c), srcs[t] + (size_t)r * NN + kp * 32 + c * 8);
        }
        CP_COMMIT();
    };

    load_slab(0, 0);
    for (int kp = 0; kp < 16; kp++) {
        if (kp < 15) {
            load_slab(kp + 1, (kp + 1) & 1);
            CP_WAIT(1);
        } else {
            CP_WAIT(0);
        }
        __syncthreads();

        uint32_t bb = sb + (kp & 1) * 32768;
        #pragma unroll
        for (int ks = 0; ks < 2; ks++) {
            uint32_t b_hi[2][4], b_lo[2][4];
            #pragma unroll
            for (int ntp = 0; ntp < 2; ntp++) {
                uint32_t row = (uint32_t)(wn * 32 + ntp * 16 + ((lane >> 3) & 1) * 8 + (lane & 7));
                uint32_t chunk = (uint32_t)(ks * 2 + (lane >> 4));
                ldsm_x4(b_hi[ntp], bb + 16384 + sw64(row, chunk));
                ldsm_x4(b_lo[ntp], bb + 24576 + sw64(row, chunk));
            }
            #pragma unroll
            for (int mt = 0; mt < 4; mt++) {
                uint32_t a_hi[4], a_lo[4];
                uint32_t off = sw64((uint32_t)(wm * 64 + mt * 16 + (lane & 15)),
                                    (uint32_t)(ks * 2 + (lane >> 4)));
                ldsm_x4(a_hi, bb + off);
                ldsm_x4(a_lo, bb + 8192 + off);
                #pragma unroll
                for (int ntp = 0; ntp < 2; ntp++) {
                    mma_bf16r(acc[mt][2*ntp],   a_hi, b_hi[ntp][0], b_hi[ntp][2]);
                    mma_bf16r(acc[mt][2*ntp],   a_hi, b_lo[ntp][0], b_lo[ntp][2]);
                    mma_bf16r(acc[mt][2*ntp],   a_lo, b_hi[ntp][0], b_hi[ntp][2]);
                    mma_bf16r(acc[mt][2*ntp+1], a_hi, b_hi[ntp][1], b_hi[ntp][3]);
                    mma_bf16r(acc[mt][2*ntp+1], a_hi, b_lo[ntp][1], b_lo[ntp][3]);
                    mma_bf16r(acc[mt][2*ntp+1], a_lo, b_hi[ntp][1], b_hi[ntp][3]);
                }
            }
        }
        __syncthreads();
    }

    #pragma unroll
    for (int mt = 0; mt < 4; mt++) {
        int i = i0 + wm * 64 + mt * 16 + (lane >> 2);
        #pragma unroll
        for (int nt = 0; nt < 4; nt++) {
            int j = j0 + wn * 32 + nt * 8 + (lane & 3) * 2;
            size_t base = (size_t)d * NROWS + (size_t)i * NN + j;
            *(float2*)&g_x[base]          = make_float2(acc[mt][nt][0], acc[mt][nt][1]);
            *(float2*)&g_x[base + 8 * NN] = make_float2(acc[mt][nt][2], acc[mt][nt][3]);
        }
    }
}

// ---- Stage 4: LN2 -> bf16 split -> HMMA, times out_gate; 512 threads ----
#define OUT_SMEM (131072 + 128*133*4)
__global__ __launch_bounds__(512) void k_out(const float* __restrict__ ln2w,
                                             const float* __restrict__ ln2b,
                                             const float* __restrict__ bout,
                                             float* __restrict__ out) {
    extern __shared__ char smc[];
    const uint32_t sb = smem_u32(smc);
    float* ys = (float*)(smc + 131072);
    const int tid = threadIdx.x;
    const int wid = tid >> 5, lane = tid & 31;
    const int row0 = blockIdx.x * 128;
    const int wm = wid >> 1, wn = wid & 1;

    #pragma unroll
    for (int p = 0; p < 8; p++) {
        int idx = tid + 512 * p;
        cp16(sb + 65536 + idx * 16, g_wimg + 5 * 65536 + idx * 16);
    }
    CP_COMMIT();

    #pragma unroll 8
    for (int p = 0; p < 32; p++) {
        int idx = tid + 512 * p;
        int row = idx & 127, dd = idx >> 7;
        ys[row * 133 + dd] = g_x[(size_t)dd * NROWS + row0 + row];
    }
    __syncthreads();

    {
        float w4[4], b4[4];
        #pragma unroll
        for (int q = 0; q < 4; q++) { w4[q] = ln2w[lane * 4 + q]; b4[q] = ln2b[lane * 4 + q]; }
        int dd = lane * 4;
        int hh = dd >> 6;
        uint32_t offb = (uint32_t)((dd & 63) * 2);
        #pragma unroll
        for (int rr = 0; rr < 8; rr++) {
            int row = wid * 8 + rr;
            float* yr = &ys[row * 133 + dd];
            float v0 = yr[0], v1 = yr[1], v2 = yr[2], v3 = yr[3];
            float s = v0 + v1 + v2 + v3;
            float q2 = v0 * v0 + v1 * v1 + v2 * v2 + v3 * v3;
            #pragma unroll
            for (int o = 16; o; o >>= 1) {
                s  += __shfl_xor_sync(0xffffffffu, s, o);
                q2 += __shfl_xor_sync(0xffffffffu, q2, o);
            }
            float mu = s * (1.0f / DD);
            float var = q2 * (1.0f / DD) - mu * mu;
            float rs = rsqrtf(var + 1e-5f);
            float n0 = (v0 - mu) * rs * w4[0] + b4[0];
            float n1 = (v1 - mu) * rs * w4[1] + b4[1];
            float n2 = (v2 - mu) * rs * w4[2] + b4[2];
            float n3 = (v3 - mu) * rs * w4[3] + b4[3];
            __nv_bfloat16 h0 = __float2bfloat16(n0), h1 = __float2bfloat16(n1);
            __nv_bfloat16 h2 = __float2bfloat16(n2), h3 = __float2bfloat16(n3);
            __nv_bfloat16 l0 = __float2bfloat16(n0 - __bfloat162float(h0));
            __nv_bfloat16 l1 = __float2bfloat16(n1 - __bfloat162float(h1));
            __nv_bfloat16 l2 = __float2bfloat16(n2 - __bfloat162float(h2));
            __nv_bfloat16 l3 = __float2bfloat16(n3 - __bfloat162float(h3));
            uint32_t off = ((uint32_t)row << 7) + offb;
            off ^= (off >> 3) & 0x70;
            *(uint2*)(smc + hh * 16384 + off)         = make_uint2(pkbf(h0, h1), pkbf(h2, h3));
            *(uint2*)(smc + 32768 + hh * 16384 + off) = make_uint2(pkbf(l0, l1), pkbf(l2, l3));
        }
    }
    CP_WAIT(0);
    __syncthreads();

    float acc[8][4];
    #pragma unroll
    for (int nf = 0; nf < 8; nf++)
        #pragma unroll
        for (int q = 0; q < 4; q++) acc[nf][q] = 0.0f;

    #pragma unroll
    for (int ks = 0; ks < 8; ks++) {
        int h = ks >> 2, kk = ks & 3;
        uint32_t b_hi[4][4], b_lo[4][4];
        #pragma unroll
        for (int nfp = 0; nfp < 4; nfp++) {
            uint32_t row = (uint32_t)(wn * 64 + nfp * 16 + ((lane >> 3) & 1) * 8 + (lane & 7));
            uint32_t off = (row << 7) + ((uint32_t)kk << 5) + ((uint32_t)(lane >> 4) << 4);
            off ^= (off >> 3) & 0x70;
            ldsm_x4(b_hi[nfp], sb + 65536 + h * 16384 + off);
            ldsm_x4(b_lo[nfp], sb + 98304 + h * 16384 + off);
        }
        uint32_t a_hi[4], a_lo[4];
        {
            uint32_t row = (uint32_t)(wm * 16 + (lane & 15));
            uint32_t off = (row << 7) + ((uint32_t)kk << 5) + ((uint32_t)(lane >> 4) << 4);
            off ^= (off >> 3) & 0x70;
            ldsm_x4(a_hi, sb + h * 16384 + off);
            ldsm_x4(a_lo, sb + 32768 + h * 16384 + off);
        }
        #pragma unroll
        for (int nfp = 0; nfp < 4; nfp++) {
            mma_bf16r(acc[2*nfp],   a_hi, b_hi[nfp][0], b_hi[nfp][2]);
            mma_bf16r(acc[2*nfp],   a_hi, b_lo[nfp][0], b_lo[nfp][2]);
            mma_bf16r(acc[2*nfp],   a_lo, b_hi[nfp][0], b_hi[nfp][2]);
            mma_bf16r(acc[2*nfp+1], a_hi, b_hi[nfp][1], b_hi[nfp][3]);
            mma_bf16r(acc[2*nfp+1], a_hi, b_lo[nfp][1], b_lo[nfp][3]);
            mma_bf16r(acc[2*nfp+1], a_lo, b_hi[nfp][1], b_hi[nfp][3]);
        }
    }

    int r = row0 + wm * 16 + (lane >> 2);
    #pragma unroll
    for (int nf = 0; nf < 8; nf++) {
        int col = wn * 64 + nf * 8 + (lane & 3) * 2;
        float b0 = bout[col], b1 = bout[col + 1];
        size_t base = (size_t)r * DD + col;
        float2 og0 = *(const float2*)&g_og[base];
        *(float2*)&out[base] = make_float2(og0.x * (acc[nf][0] + b0),
                                           og0.y * (acc[nf][1] + b1));
        float2 og1 = *(const float2*)&g_og[base + 8 * DD];
        *(float2*)&out[base + 8 * DD] = make_float2(og1.x * (acc[nf][2] + b0),
                                                    og1.y * (acc[nf][3] + b1));
    }
}

extern "C" void kernel_launch(void* const* d_in, const int* in_sizes, int n_in,
                              void* d_out, int out_size) {
    const float* edges = (const float*)d_in[0];
    const void*  mask  = d_in[1];
    const float* ln1w  = (const float*)d_in[2];
    const float* ln1b  = (const float*)d_in[3];
    const float* Wfg   = (const float*)d_in[4];
    const float* bfg   = (const float*)d_in[5];
    const float* Wgo   = (const float*)d_in[6];
    const float* bgo   = (const float*)d_in[7];
    const float* ln2w  = (const float*)d_in[8];
    const float* ln2b  = (const float*)d_in[9];
    const float* Wout  = (const float*)d_in[10];
    const float* bout  = (const float*)d_in[11];
    float* out = (float*)d_out;

    cudaFuncSetAttribute(k_fg,  cudaFuncAttributeMaxDynamicSharedMemorySize, FG_SMEM);
    cudaFuncSetAttribute(k_tri, cudaFuncAttributeMaxDynamicSharedMemorySize, TRI_SMEM);
    cudaFuncSetAttribute(k_out, cudaFuncAttributeMaxDynamicSharedMemorySize, OUT_SMEM);

    k_detect<<<1, 256>>>((const unsigned int*)mask);
    k_wsplit<<<6, 256>>>(Wfg, Wgo, Wout);
    k_ln<<<NROWS / 8, 256>>>(edges, ln1w, ln1b);
    k_fg<<<NROWS / 128, 512, FG_SMEM>>>(mask, bfg, bgo);
    k_tri<<<dim3(NN / 128, NN / 128, DD), 256, TRI_SMEM>>>();
    k_out<<<NROWS / 128, 512, OUT_SMEM>>>(ln2w, ln2b, bout, out);
}